// round 12
// baseline (speedup 1.0000x reference)
#include <cuda_runtime.h>
#include <cuda_bf16.h>
#include <cuda_fp16.h>
#include <cstdint>
#include <cstddef>

// ---------------- problem constants ----------------
#define TT      64
#define MM      64
#define NROWS   4096      // T*M
#define ROI     2048
#define SPA     4
#define WORD    300
#define ROISPA  2052      // ROI+SPA
#define INW     2352      // ROI+SPA+WORD
#define HH      512
#define DD      256
#define RELIN   556       // D + WORD
#define KP1     2080      // ROISPA padded to 65*32

// ---------------- scratch (device globals; no allocation) ----------------
__device__ __half g_X16 [NROWS * KP1];                      // activations fp16
__device__ __half g_W1_s[HH * KP1], g_W1_o[HH * KP1];       // weights fp16
__device__ __half g_Y1_s[NROWS * HH], g_Y1_o[NROWS * HH];
__device__ __half g_Y2_s[NROWS * HH], g_Y2_o[NROWS * HH];
__device__ __half g_Wf_s[HH * HH], g_Wf_o[HH * HH];
__device__ __half g_Wcc_s[HH * HH], g_Wcc_o[HH * HH];
__device__ float g_A[NROWS * HH];      // A + bias512 folded in
__device__ float g_B[NROWS * HH];
__device__ float g_Wsum_s[HH * DD], g_Wsum_o[HH * DD];
__device__ float g_Wc_s  [HH * DD], g_Wc_o  [HH * DD];
__device__ float g_c_subj[HH], g_c_obj[HH], g_bias512[HH];
__device__ float g_bf_s[HH], g_bf_o[HH], g_cvec_s[HH], g_cvec_o[HH];
__device__ __half g_W2[DD * HH];

// ---------------- helpers ----------------
__device__ __forceinline__ uint32_t smem_u32(const void* p) {
    uint32_t a;
    asm("{ .reg .u64 t; cvta.to.shared.u64 t, %1; cvt.u32.u64 %0, t; }"
        : "=r"(a) : "l"(p));
    return a;
}
__device__ __forceinline__ void ldsm4(uint32_t* r, uint32_t addr) {
    asm volatile("ldmatrix.sync.aligned.m8n8.x4.shared.b16 {%0,%1,%2,%3}, [%4];"
        : "=r"(r[0]), "=r"(r[1]), "=r"(r[2]), "=r"(r[3]) : "r"(addr));
}
__device__ __forceinline__ void mma_f16(float* c, const uint32_t* a, const uint32_t* b) {
    asm volatile(
        "mma.sync.aligned.m16n8k16.row.col.f32.f16.f16.f32 "
        "{%0,%1,%2,%3}, {%4,%5,%6,%7}, {%8,%9}, {%0,%1,%2,%3};"
        : "+f"(c[0]), "+f"(c[1]), "+f"(c[2]), "+f"(c[3])
        : "r"(a[0]), "r"(a[1]), "r"(a[2]), "r"(a[3]), "r"(b[0]), "r"(b[1]));
}
__device__ __forceinline__ void cp16(uint32_t dst, const void* src) {
    asm volatile("cp.async.ca.shared.global [%0], [%1], 16;" :: "r"(dst), "l"(src));
}
__device__ __forceinline__ void cp_commit() {
    asm volatile("cp.async.commit_group;");
}
__device__ __forceinline__ void cp_wait0() {
    asm volatile("cp.async.wait_group 0;" ::: "memory");
}

// ---------------- pack X = [roi | spatial | 0pad] -> fp16 ----------------
__global__ void pack_x_kernel(const float* __restrict__ roi,
                              const float* __restrict__ spa) {
    int r = blockIdx.x;
    for (int k = threadIdx.x; k < KP1; k += blockDim.x) {
        float v = 0.f;
        if (k < ROI)         v = roi[(size_t)r * ROI + k];
        else if (k < ROISPA) v = spa[(size_t)r * SPA + (k - ROI)];
        g_X16[(size_t)r * KP1 + k] = __float2half_rn(v);
    }
}

// ---------------- convert layer-1 weights -> fp16 ----------------
__global__ void split_w1_kernel(const float* __restrict__ s_w1,
                                const float* __restrict__ o_w1) {
    int idx = blockIdx.x * 256 + threadIdx.x;
    if (idx >= HH * KP1) return;
    int n = idx / KP1, k = idx - n * KP1;
    float vs = (k < ROISPA) ? s_w1[(size_t)n * INW + k] : 0.f;
    float vo = (k < ROISPA) ? o_w1[(size_t)n * INW + k] : 0.f;
    g_W1_s[idx] = __float2half_rn(vs);
    g_W1_o[idx] = __float2half_rn(vo);
}

// ---------------- convert rel_w2 -> fp16 ----------------
__global__ void split_w2_kernel(const float* __restrict__ w2) {
    int idx = blockIdx.x * 256 + threadIdx.x;
    g_W2[idx] = __float2half_rn(w2[idx]);
}

// ---------------- constant biases + Wsum ----------------
__global__ void pre_vec_kernel(const float* __restrict__ subj_w1, const float* __restrict__ subj_b1,
                               const float* __restrict__ obj_w1,  const float* __restrict__ obj_b1,
                               const float* __restrict__ rel_w1,  const float* __restrict__ rel_b1,
                               const float* __restrict__ subj_emb, const float* __restrict__ obj_emb,
                               const float* __restrict__ pred_emb,
                               const float* __restrict__ fuse_s_w1, const float* __restrict__ fuse_o_w1) {
    int h = blockIdx.x;
    int t = threadIdx.x;
    float s1 = 0.f, s2 = 0.f, s3 = 0.f;
    for (int w = t; w < WORD; w += 128) {
        s1 += subj_w1[(size_t)h * INW + ROISPA + w] * subj_emb[w];
        s2 += obj_w1 [(size_t)h * INW + ROISPA + w] * obj_emb[w];
        s3 += rel_w1 [(size_t)h * RELIN + DD + w]   * pred_emb[w];
    }
    for (int o = 16; o > 0; o >>= 1) {
        s1 += __shfl_down_sync(0xffffffffu, s1, o);
        s2 += __shfl_down_sync(0xffffffffu, s2, o);
        s3 += __shfl_down_sync(0xffffffffu, s3, o);
    }
    __shared__ float red[3][4];
    int wrp = t >> 5, lan = t & 31;
    if (lan == 0) { red[0][wrp] = s1; red[1][wrp] = s2; red[2][wrp] = s3; }
    __syncthreads();
    if (t == 0) {
        g_c_subj[h]  = red[0][0] + red[0][1] + red[0][2] + red[0][3] + subj_b1[h];
        g_c_obj[h]   = red[1][0] + red[1][1] + red[1][2] + red[1][3] + obj_b1[h];
        g_bias512[h] = red[2][0] + red[2][1] + red[2][2] + red[2][3] + rel_b1[h];
    }
    for (int d = t; d < DD; d += 128) {
        g_Wsum_s[h * DD + d] = fuse_s_w1[(size_t)h * (2*DD) + d] + fuse_s_w1[(size_t)h * (2*DD) + DD + d];
        g_Wsum_o[h * DD + d] = fuse_o_w1[(size_t)h * (2*DD) + d] + fuse_o_w1[(size_t)h * (2*DD) + DD + d];
    }
}

// ---------------- tiled NN GEMM: C = A(MxK) @ B(KxN) ----------------
template<bool F16OUT>
__global__ __launch_bounds__(256)
void nn_gemm_kernel(const float* __restrict__ A0, const float* __restrict__ B0,
                    float* __restrict__ C0, __half* __restrict__ Ch0,
                    const float* __restrict__ A1, const float* __restrict__ B1,
                    float* __restrict__ C1, __half* __restrict__ Ch1,
                    int N, int K, int lda, int ldb) {
    __shared__ float Ask[16][68];
    __shared__ float Bs [16][68];
    const int br = blockIdx.z;
    const float* A = br ? A1 : A0;
    const float* B = br ? B1 : B0;
    const int m0 = blockIdx.y * 64, n0 = blockIdx.x * 64;
    const int tid = threadIdx.x;
    const int tr = tid >> 4, tc = tid & 15;
    float acc[4][4];
    #pragma unroll
    for (int i = 0; i < 4; i++)
        #pragma unroll
        for (int j = 0; j < 4; j++) acc[i][j] = 0.f;

    for (int k0 = 0; k0 < K; k0 += 16) {
        {
            int r = tid >> 2, kq = (tid & 3) * 4;
            float4 v = *reinterpret_cast<const float4*>(&A[(size_t)(m0 + r) * lda + k0 + kq]);
            Ask[kq + 0][r] = v.x; Ask[kq + 1][r] = v.y;
            Ask[kq + 2][r] = v.z; Ask[kq + 3][r] = v.w;
        }
        {
            int k = tid >> 4, nq = (tid & 15) * 4;
            float4 v = *reinterpret_cast<const float4*>(&B[(size_t)(k0 + k) * ldb + n0 + nq]);
            *reinterpret_cast<float4*>(&Bs[k][nq]) = v;
        }
        __syncthreads();
        #pragma unroll
        for (int k = 0; k < 16; k++) {
            float a[4], b[4];
            *reinterpret_cast<float4*>(a) = *reinterpret_cast<const float4*>(&Ask[k][tr * 4]);
            *reinterpret_cast<float4*>(b) = *reinterpret_cast<const float4*>(&Bs[k][tc * 4]);
            #pragma unroll
            for (int i = 0; i < 4; i++)
                #pragma unroll
                for (int j = 0; j < 4; j++)
                    acc[i][j] = fmaf(a[i], b[j], acc[i][j]);
        }
        __syncthreads();
    }

    if (F16OUT) {
        __half* Ch = br ? Ch1 : Ch0;
        #pragma unroll
        for (int i = 0; i < 4; i++)
            #pragma unroll
            for (int j = 0; j < 4; j++) {
                size_t off = (size_t)(m0 + tr * 4 + i) * N + n0 + tc * 4 + j;
                Ch[off] = __float2half_rn(acc[i][j]);
            }
    } else {
        float* C = br ? C1 : C0;
        #pragma unroll
        for (int i = 0; i < 4; i++)
            #pragma unroll
            for (int j = 0; j < 4; j++)
                C[(size_t)(m0 + tr * 4 + i) * N + n0 + tc * 4 + j] = acc[i][j];
    }
}

// ---------------- batched small GEMV for bias folds ----------------
__global__ void gemv4_kernel(const float* __restrict__ subj_b2, const float* __restrict__ obj_b2,
                             const float* __restrict__ fuse_s_b1, const float* __restrict__ fuse_o_b1,
                             const float* __restrict__ fuse_s_b2, const float* __restrict__ fuse_o_b2) {
    int which = blockIdx.y;
    const float *A, *v, *add; float* o;
    if      (which == 0) { A = g_Wsum_s; v = subj_b2;  add = fuse_s_b1; o = g_bf_s; }
    else if (which == 1) { A = g_Wsum_o; v = obj_b2;   add = fuse_o_b1; o = g_bf_o; }
    else if (which == 2) { A = g_Wc_s;   v = fuse_s_b2; add = g_bias512; o = g_cvec_s; }
    else                 { A = g_Wc_o;   v = fuse_o_b2; add = nullptr;  o = g_cvec_o; }
    int h = blockIdx.x * 8 + (threadIdx.x >> 5);
    int lane = threadIdx.x & 31;
    float s = 0.f;
    for (int d = lane; d < DD; d += 32) s += A[h * DD + d] * v[d];
    #pragma unroll
    for (int off = 16; off > 0; off >>= 1) s += __shfl_down_sync(0xffffffffu, s, off);
    if (lane == 0) o[h] = s + (add ? add[h] : 0.f);
}

// ================= chain HMMA GEMM (fp16, cp.async double-buffered) ====
// planes per buffer: X (10240) | W (10240)
#define CPSTR   80
#define CBUFSZ  20480
#define CSMEM   (512 + 2 * CBUFSZ)   // 41472

template<bool RELU, bool F16OUT>
__global__ __launch_bounds__(256, 2)
void chain_hmma_kernel(const __half* __restrict__ X0, const __half* __restrict__ X1,
                       int ldx,
                       const __half* __restrict__ W0, const __half* __restrict__ W1,
                       const float* __restrict__ bias0, const float* __restrict__ bias1,
                       float* __restrict__ C0, float* __restrict__ C1,
                       __half* __restrict__ Co0, __half* __restrict__ Co1,
                       int N, int K) {
    extern __shared__ char smem[];
    const uint32_t su = smem_u32(smem);
    float* biasS = reinterpret_cast<float*>(smem);

    const int tid  = threadIdx.x;
    const int wid  = tid >> 5;
    const int lane = tid & 31;
    const int wm   = wid >> 1;
    const int wn   = wid & 1;
    const int n0   = blockIdx.x * 128;
    const int m0   = blockIdx.y * 128;
    const int br   = blockIdx.z;

    const __half* X = br ? X1 : X0;
    const __half* W = br ? W1 : W0;
    const float* bias = br ? bias1 : bias0;

    if (tid < 128) biasS[tid] = bias[n0 + tid];

    auto stage = [&](int k0, int b) {
        uint32_t base = su + 512 + (uint32_t)b * CBUFSZ;
        #pragma unroll
        for (int e = 0; e < 2; e++) {
            int idx = e * 256 + tid;
            int r = idx >> 2, q = idx & 3;
            cp16(base +         r * CPSTR + q * 16, X + (size_t)(m0 + r) * ldx + k0 + q * 8);
            cp16(base + 10240 + r * CPSTR + q * 16, W + (size_t)(n0 + r) * K + k0 + q * 8);
        }
    };

    const uint32_t h_off = (uint32_t)((lane & 15) * CPSTR + (lane >> 4) * 16);
    const uint32_t w_off = (uint32_t)(((lane & 7) + ((lane >> 4) << 3)) * CPSTR
                                      + ((lane >> 3) & 1) * 16);

    float acc[2][8][4];
    #pragma unroll
    for (int mb = 0; mb < 2; mb++)
        #pragma unroll
        for (int nb = 0; nb < 8; nb++)
            #pragma unroll
            for (int q = 0; q < 4; q++) acc[mb][nb][q] = 0.f;

    stage(0, 0); cp_commit();
    const int nk = K / 32;

    for (int c = 0; c < nk; c++) {
        cp_wait0();
        __syncthreads();
        if (c + 1 < nk) { stage((c + 1) * 32, (c + 1) & 1); cp_commit(); }

        const uint32_t base = su + 512 + (uint32_t)(c & 1) * CBUFSZ;
        #pragma unroll
        for (int ks = 0; ks < 2; ks++) {
            uint32_t a[2][4];
            const uint32_t hbase = base + wm * (32 * CPSTR) + ks * 32 + h_off;
            ldsm4(a[0], hbase);
            ldsm4(a[1], hbase + 16 * CPSTR);
            const uint32_t wbase = base + 10240 + wn * (64 * CPSTR) + ks * 32 + w_off;
            #pragma unroll
            for (int g = 0; g < 4; g++) {
                uint32_t b[4];
                ldsm4(b, wbase + g * (16 * CPSTR));
                mma_f16(acc[0][g * 2 + 0], a[0], b);
                mma_f16(acc[0][g * 2 + 1], a[0], b + 2);
                mma_f16(acc[1][g * 2 + 0], a[1], b);
                mma_f16(acc[1][g * 2 + 1], a[1], b + 2);
            }
        }
    }

    // ---- epilogue ----
    const int qr = lane >> 2, qc = (lane & 3) * 2;
    float* C = br ? C1 : C0;
    __half* Co = br ? Co1 : Co0;
    #pragma unroll
    for (int mb = 0; mb < 2; mb++) {
        int rA = m0 + wm * 32 + mb * 16 + qr;
        int rB = rA + 8;
        #pragma unroll
        for (int nb = 0; nb < 8; nb++) {
            int ln = qc + wn * 64 + nb * 8;
            int col = n0 + ln;
            float vA0 = acc[mb][nb][0] + biasS[ln];
            float vA1 = acc[mb][nb][1] + biasS[ln + 1];
            float vB0 = acc[mb][nb][2] + biasS[ln];
            float vB1 = acc[mb][nb][3] + biasS[ln + 1];
            if (RELU) {
                vA0 = fmaxf(vA0, 0.f); vA1 = fmaxf(vA1, 0.f);
                vB0 = fmaxf(vB0, 0.f); vB1 = fmaxf(vB1, 0.f);
            }
            if (F16OUT) {
                *reinterpret_cast<__half2*>(&Co[(size_t)rA * N + col]) = __floats2half2_rn(vA0, vA1);
                *reinterpret_cast<__half2*>(&Co[(size_t)rB * N + col]) = __floats2half2_rn(vB0, vB1);
            } else {
                *reinterpret_cast<float2*>(&C[(size_t)rA * N + col]) = make_float2(vA0, vA1);
                *reinterpret_cast<float2*>(&C[(size_t)rB * N + col]) = make_float2(vB0, vB1);
            }
        }
    }
}

// ================= HMMA pairwise kernel (fp16, full N=256 per CTA) ======
// 512 threads = 16 warps (4m x 4n). CTA tile: 128 pairs x 256 N.
// smem layout:
//  0      b2        1024
//  1024   H (fp16)  10240
//  11264  buf0 { A 2x128B=256 | B 64x144=9216 | W 256x80=20480 } = 29952
//  41216  buf1
#define PW_H     1024
#define PW_BUF0  11264
#define PW_BUFSZ 29952
#define PSTR     80
#define PSMEM    (PW_BUF0 + 2 * PW_BUFSZ)   // 71168

__global__ __launch_bounds__(512, 1)
void pairwise_hmma_kernel(const float* __restrict__ b2v,
                          float* __restrict__ out) {
    extern __shared__ char smem[];
    const uint32_t su = smem_u32(smem);
    float* bs2 = reinterpret_cast<float*>(smem);

    const int tid  = threadIdx.x;
    const int wid  = tid >> 5;
    const int lane = tid & 31;
    const int wm   = wid >> 2;           // 0..3 (32-row m tile)
    const int wn   = wid & 3;            // 0..3 (64-col n tile)

    const int ib2 = blockIdx.x * 2;
    const int t   = blockIdx.y;

    if (tid < 256) bs2[tid] = b2v[tid];

    const size_t arow0 = (size_t)(t * 64 + ib2) * HH;
    const size_t brow0 = (size_t)(t * 64) * HH;

    auto stage = [&](int k0, int b) {
        uint32_t base = su + PW_BUF0 + (uint32_t)b * PW_BUFSZ;
        if (tid < 16) {                            // A (bias pre-folded): 2 rows x 32 f
            int r = tid >> 3, q = tid & 7;
            cp16(base + r * 128 + q * 16, g_A + arow0 + (size_t)r * HH + k0 + q * 4);
        }
        {                                          // B: 64 x 32 f, stride 144B (512 cp16)
            int j = tid >> 3, q = tid & 7;
            cp16(base + 256 + j * 144 + q * 16, g_B + brow0 + (size_t)j * HH + k0 + q * 4);
        }
        #pragma unroll
        for (int e = 0; e < 2; e++) {              // W: 256 x 32 fp16 (1024 cp16)
            int idx = e * 512 + tid;
            int n = idx >> 2, q = idx & 3;
            cp16(base + 9472 + n * PSTR + q * 16, g_W2 + (size_t)n * HH + k0 + q * 8);
        }
    };

    const uint32_t h_off = (uint32_t)((lane & 15) * PSTR + (lane >> 4) * 16);
    const uint32_t w_off = (uint32_t)(((lane & 7) + ((lane >> 4) << 3)) * PSTR
                                      + ((lane >> 3) & 1) * 16);

    float acc[2][8][4];
    #pragma unroll
    for (int mb = 0; mb < 2; mb++)
        #pragma unroll
        for (int nb = 0; nb < 8; nb++)
            #pragma unroll
            for (int q = 0; q < 4; q++) acc[mb][nb][q] = 0.f;

    stage(0, 0); cp_commit();

    for (int c = 0; c < 16; c++) {
        cp_wait0();
        __syncthreads();                 // buf(c) ready; all mma(c-1) reads done
        if (c + 1 < 16) { stage((c + 1) * 32, (c + 1) & 1); cp_commit(); }

        const uint32_t bo = PW_BUF0 + (uint32_t)(c & 1) * PW_BUFSZ;
        const float* AsB = reinterpret_cast<const float*>(smem + bo);
        const float* BsB = reinterpret_cast<const float*>(smem + bo + 256);

        // ---- build H (128 x 32 fp16), bias pre-folded into A ----
        #pragma unroll
        for (int e = 0; e < 4; e++) {
            int idx = e * 512 + tid;     // 0..2047
            int p  = idx >> 4;
            int kp = idx & 15;
            int k  = kp * 2;
            int i  = p >> 6, j = p & 63;
            float2 av = *reinterpret_cast<const float2*>(&AsB[i * 32 + k]);
            float2 bv = *reinterpret_cast<const float2*>(&BsB[j * 36 + k]);
            float v0 = fmaxf(av.x - bv.x, 0.f);
            float v1 = fmaxf(av.y - bv.y, 0.f);
            *reinterpret_cast<__half2*>(smem + PW_H + p * PSTR + k * 2) =
                __floats2half2_rn(v0, v1);
        }
        __syncthreads();                 // H staged

        const uint32_t base = su + bo;
        #pragma unroll
        for (int ks = 0; ks < 2; ks++) {
            uint32_t a[2][4];
            const uint32_t hbase = su + PW_H + wm * (32 * PSTR) + ks * 32 + h_off;
            ldsm4(a[0], hbase);
            ldsm4(a[1], hbase + 16 * PSTR);
            const uint32_t wbase = base + 9472 + wn * (64 * PSTR) + ks * 32 + w_off;
            #pragma unroll
            for (int g = 0; g < 4; g++) {
                uint32_t b[4];
                ldsm4(b, wbase + g * (16 * PSTR));
                mma_f16(acc[0][g * 2 + 0], a[0], b);
                mma_f16(acc[0][g * 2 + 1], a[0], b + 2);
                mma_f16(acc[1][g * 2 + 0], a[1], b);
                mma_f16(acc[1][g * 2 + 1], a[1], b + 2);
            }
        }
    }

    const int qr = lane >> 2, qc = (lane & 3) * 2;
    #pragma unroll
    for (int mb = 0; mb < 2; mb++) {
        int rA = wm * 32 + mb * 16 + qr;
        int rB = rA + 8;
        float* oA = out + ((size_t)(t * 64 + ib2 + (rA >> 6)) * 64 + (rA & 63)) * 256
                        + wn * 64 + qc;
        float* oB = out + ((size_t)(t * 64 + ib2 + (rB >> 6)) * 64 + (rB & 63)) * 256
                        + wn * 64 + qc;
        #pragma unroll
        for (int nb = 0; nb < 8; nb++) {
            int ln = wn * 64 + nb * 8 + qc;
            float2 vA = make_float2(acc[mb][nb][0] + bs2[ln],
                                    acc[mb][nb][1] + bs2[ln + 1]);
            float2 vB = make_float2(acc[mb][nb][2] + bs2[ln],
                                    acc[mb][nb][3] + bs2[ln + 1]);
            *reinterpret_cast<float2*>(oA + nb * 8) = vA;
            *reinterpret_cast<float2*>(oB + nb * 8) = vB;
        }
    }
}

// ---------------- host launch ----------------
extern "C" void kernel_launch(void* const* d_in, const int* in_sizes, int n_in,
                              void* d_out, int out_size) {
    const float* roi       = (const float*)d_in[0];
    const float* spatial   = (const float*)d_in[1];
    const float* subj_emb  = (const float*)d_in[3];
    const float* obj_emb   = (const float*)d_in[4];
    const float* pred_emb  = (const float*)d_in[5];
    const float* subj_w1   = (const float*)d_in[6];
    const float* subj_b1   = (const float*)d_in[7];
    const float* subj_w2   = (const float*)d_in[8];
    const float* subj_b2   = (const float*)d_in[9];
    const float* obj_w1    = (const float*)d_in[10];
    const float* obj_b1    = (const float*)d_in[11];
    const float* obj_w2    = (const float*)d_in[12];
    const float* obj_b2    = (const float*)d_in[13];
    const float* fuse_s_w1 = (const float*)d_in[14];
    const float* fuse_s_b1 = (const float*)d_in[15];
    const float* fuse_s_w2 = (const float*)d_in[16];
    const float* fuse_s_b2 = (const float*)d_in[17];
    const float* fuse_o_w1 = (const float*)d_in[18];
    const float* fuse_o_b1 = (const float*)d_in[19];
    const float* fuse_o_w2 = (const float*)d_in[20];
    const float* fuse_o_b2 = (const float*)d_in[21];
    const float* W_rs      = (const float*)d_in[22];
    const float* W_ro      = (const float*)d_in[23];
    const float* rel_w1    = (const float*)d_in[24];
    const float* rel_b1    = (const float*)d_in[25];
    const float* rel_w2    = (const float*)d_in[26];
    const float* rel_b2    = (const float*)d_in[27];
    float* out = (float*)d_out;

    __half *pX16, *pW1_s, *pW1_o;
    __half *pY1_s, *pY1_o, *pY2_s, *pY2_o;
    __half *pWf_s, *pWf_o, *pWcc_s, *pWcc_o;
    float *pA, *pB, *pWsum_s, *pWsum_o, *pWc_s, *pWc_o;
    float *pc_subj, *pc_obj, *pbf_s, *pbf_o, *pcv_s, *pcv_o;
    cudaGetSymbolAddress((void**)&pX16, g_X16);
    cudaGetSymbolAddress((void**)&pW1_s, g_W1_s);
    cudaGetSymbolAddress((void**)&pW1_o, g_W1_o);
    cudaGetSymbolAddress((void**)&pY1_s, g_Y1_s);
    cudaGetSymbolAddress((void**)&pY1_o, g_Y1_o);
    cudaGetSymbolAddress((void**)&pY2_s, g_Y2_s);
    cudaGetSymbolAddress((void**)&pY2_o, g_Y2_o);
    cudaGetSymbolAddress((void**)&pWf_s, g_Wf_s);
    cudaGetSymbolAddress((void**)&pWf_o, g_Wf_o);
    cudaGetSymbolAddress((void**)&pWcc_s, g_Wcc_s);
    cudaGetSymbolAddress((void**)&pWcc_o, g_Wcc_o);
    cudaGetSymbolAddress((void**)&pA, g_A);
    cudaGetSymbolAddress((void**)&pB, g_B);
    cudaGetSymbolAddress((void**)&pWsum_s, g_Wsum_s);
    cudaGetSymbolAddress((void**)&pWsum_o, g_Wsum_o);
    cudaGetSymbolAddress((void**)&pWc_s, g_Wc_s);
    cudaGetSymbolAddress((void**)&pWc_o, g_Wc_o);
    cudaGetSymbolAddress((void**)&pc_subj, g_c_subj);
    cudaGetSymbolAddress((void**)&pc_obj,  g_c_obj);
    cudaGetSymbolAddress((void**)&pbf_s,  g_bf_s);
    cudaGetSymbolAddress((void**)&pbf_o,  g_bf_o);
    cudaGetSymbolAddress((void**)&pcv_s,  g_cvec_s);
    cudaGetSymbolAddress((void**)&pcv_o,  g_cvec_o);

    static bool attr_set = false;
    if (!attr_set) {
        cudaFuncSetAttribute(pairwise_hmma_kernel,
                             cudaFuncAttributeMaxDynamicSharedMemorySize, PSMEM);
        cudaFuncSetAttribute(chain_hmma_kernel<true, true>,
                             cudaFuncAttributeMaxDynamicSharedMemorySize, CSMEM);
        cudaFuncSetAttribute(chain_hmma_kernel<false, false>,
                             cudaFuncAttributeMaxDynamicSharedMemorySize, CSMEM);
        attr_set = true;
    }

    // 1. pack + precompute
    pack_x_kernel<<<NROWS, 256>>>(roi, spatial);
    split_w1_kernel<<<(HH * KP1 + 255) / 256, 256>>>(subj_w1, obj_w1);
    split_w2_kernel<<<512, 256>>>(rel_w2);
    pre_vec_kernel<<<HH, 128>>>(subj_w1, subj_b1, obj_w1, obj_b1, rel_w1, rel_b1,
                                subj_emb, obj_emb, pred_emb, fuse_s_w1, fuse_o_w1);
    nn_gemm_kernel<false><<<dim3(4, 8, 2), 256>>>(
        rel_w1, W_rs, pWc_s, nullptr,
        rel_w1, W_ro, pWc_o, nullptr,
        DD, DD, RELIN, DD);
    nn_gemm_kernel<true><<<dim3(8, 8, 2), 256>>>(
        pWsum_s, subj_w2, nullptr, pWf_s,
        pWsum_o, obj_w2,  nullptr, pWf_o,
        HH, DD, DD, HH);
    nn_gemm_kernel<true><<<dim3(8, 8, 2), 256>>>(
        pWc_s, fuse_s_w2, nullptr, pWcc_s,
        pWc_o, fuse_o_w2, nullptr, pWcc_o,
        HH, DD, DD, HH);
    gemv4_kernel<<<dim3(64, 4), 256>>>(subj_b2, obj_b2, fuse_s_b1, fuse_o_b1,
                                       fuse_s_b2, fuse_o_b2);

    dim3 cgrid(HH / 128, NROWS / 128, 2);

    // 2. layer 1: relu(X @ W1^T + c) -> Y1 fp16
    chain_hmma_kernel<true, true><<<cgrid, 256, CSMEM>>>(
        pX16, pX16, KP1,
        pW1_s, pW1_o,
        pc_subj, pc_obj,
        nullptr, nullptr,
        pY1_s, pY1_o,
        HH, KP1);

    // 3. layer 2: relu(Y1 @ Wf^T + bf) -> Y2 fp16
    chain_hmma_kernel<true, true><<<cgrid, 256, CSMEM>>>(
        pY1_s, pY1_o, HH,
        pWf_s, pWf_o,
        pbf_s, pbf_o,
        nullptr, nullptr,
        pY2_s, pY2_o,
        HH, HH);

    // 4. layer 3: Y2 @ Wcc^T + cvec(+bias512 for A) -> A/B fp32
    chain_hmma_kernel<false, false><<<cgrid, 256, CSMEM>>>(
        pY2_s, pY2_o, HH,
        pWcc_s, pWcc_o,
        pcv_s, pcv_o,
        pA, pB,
        nullptr, nullptr,
        HH, HH);

    // 5. pairwise GEMM (HMMA fp16, full-N CTAs)
    pairwise_hmma_kernel<<<dim3(32, 64), 512, PSMEM>>>(rel_b2, out);

    (void)in_sizes; (void)n_in; (void)out_size;
}

// round 13
// speedup vs baseline: 1.0849x; 1.0849x over previous
#include <cuda_runtime.h>
#include <cuda_bf16.h>
#include <cuda_fp16.h>
#include <cstdint>
#include <cstddef>

// ---------------- problem constants ----------------
#define TT      64
#define MM      64
#define NROWS   4096      // T*M
#define ROI     2048
#define SPA     4
#define WORD    300
#define ROISPA  2052      // ROI+SPA
#define INW     2352      // ROI+SPA+WORD
#define HH      512
#define DD      256
#define RELIN   556       // D + WORD
#define KP1     2080      // ROISPA padded to 65*32

// ---------------- scratch (device globals; no allocation) ----------------
__device__ __half g_X16 [NROWS * KP1];                      // activations fp16
__device__ __half g_W1_s[HH * KP1], g_W1_o[HH * KP1];       // weights fp16
__device__ __half g_Y1_s[NROWS * HH], g_Y1_o[NROWS * HH];
__device__ __half g_Y2_s[NROWS * HH], g_Y2_o[NROWS * HH];
__device__ __half g_Wf_s[HH * HH], g_Wf_o[HH * HH];
__device__ __half g_Wcc_s[HH * HH], g_Wcc_o[HH * HH];
__device__ __half g_A16[NROWS * HH];   // A + bias512 folded, fp16
__device__ __half g_B16[NROWS * HH];   // B, fp16
__device__ float g_Wsum_s[HH * DD], g_Wsum_o[HH * DD];
__device__ float g_Wc_s  [HH * DD], g_Wc_o  [HH * DD];
__device__ float g_c_subj[HH], g_c_obj[HH], g_bias512[HH];
__device__ float g_bf_s[HH], g_bf_o[HH], g_cvec_s[HH], g_cvec_o[HH];
__device__ __half g_W2[DD * HH];

// ---------------- helpers ----------------
__device__ __forceinline__ uint32_t smem_u32(const void* p) {
    uint32_t a;
    asm("{ .reg .u64 t; cvta.to.shared.u64 t, %1; cvt.u32.u64 %0, t; }"
        : "=r"(a) : "l"(p));
    return a;
}
__device__ __forceinline__ void ldsm4(uint32_t* r, uint32_t addr) {
    asm volatile("ldmatrix.sync.aligned.m8n8.x4.shared.b16 {%0,%1,%2,%3}, [%4];"
        : "=r"(r[0]), "=r"(r[1]), "=r"(r[2]), "=r"(r[3]) : "r"(addr));
}
__device__ __forceinline__ void mma_f16(float* c, const uint32_t* a, const uint32_t* b) {
    asm volatile(
        "mma.sync.aligned.m16n8k16.row.col.f32.f16.f16.f32 "
        "{%0,%1,%2,%3}, {%4,%5,%6,%7}, {%8,%9}, {%0,%1,%2,%3};"
        : "+f"(c[0]), "+f"(c[1]), "+f"(c[2]), "+f"(c[3])
        : "r"(a[0]), "r"(a[1]), "r"(a[2]), "r"(a[3]), "r"(b[0]), "r"(b[1]));
}
__device__ __forceinline__ void cp16(uint32_t dst, const void* src) {
    asm volatile("cp.async.ca.shared.global [%0], [%1], 16;" :: "r"(dst), "l"(src));
}
__device__ __forceinline__ void cp_commit() {
    asm volatile("cp.async.commit_group;");
}
__device__ __forceinline__ void cp_wait0() {
    asm volatile("cp.async.wait_group 0;" ::: "memory");
}

// ---------------- pack X = [roi | spatial | 0pad] -> fp16 ----------------
__global__ void pack_x_kernel(const float* __restrict__ roi,
                              const float* __restrict__ spa) {
    int r = blockIdx.x;
    for (int k = threadIdx.x; k < KP1; k += blockDim.x) {
        float v = 0.f;
        if (k < ROI)         v = roi[(size_t)r * ROI + k];
        else if (k < ROISPA) v = spa[(size_t)r * SPA + (k - ROI)];
        g_X16[(size_t)r * KP1 + k] = __float2half_rn(v);
    }
}

// ---------------- convert layer-1 weights -> fp16 ----------------
__global__ void split_w1_kernel(const float* __restrict__ s_w1,
                                const float* __restrict__ o_w1) {
    int idx = blockIdx.x * 256 + threadIdx.x;
    if (idx >= HH * KP1) return;
    int n = idx / KP1, k = idx - n * KP1;
    float vs = (k < ROISPA) ? s_w1[(size_t)n * INW + k] : 0.f;
    float vo = (k < ROISPA) ? o_w1[(size_t)n * INW + k] : 0.f;
    g_W1_s[idx] = __float2half_rn(vs);
    g_W1_o[idx] = __float2half_rn(vo);
}

// ---------------- convert rel_w2 -> fp16 ----------------
__global__ void split_w2_kernel(const float* __restrict__ w2) {
    int idx = blockIdx.x * 256 + threadIdx.x;
    g_W2[idx] = __float2half_rn(w2[idx]);
}

// ---------------- constant biases + Wsum ----------------
__global__ void pre_vec_kernel(const float* __restrict__ subj_w1, const float* __restrict__ subj_b1,
                               const float* __restrict__ obj_w1,  const float* __restrict__ obj_b1,
                               const float* __restrict__ rel_w1,  const float* __restrict__ rel_b1,
                               const float* __restrict__ subj_emb, const float* __restrict__ obj_emb,
                               const float* __restrict__ pred_emb,
                               const float* __restrict__ fuse_s_w1, const float* __restrict__ fuse_o_w1) {
    int h = blockIdx.x;
    int t = threadIdx.x;
    float s1 = 0.f, s2 = 0.f, s3 = 0.f;
    for (int w = t; w < WORD; w += 128) {
        s1 += subj_w1[(size_t)h * INW + ROISPA + w] * subj_emb[w];
        s2 += obj_w1 [(size_t)h * INW + ROISPA + w] * obj_emb[w];
        s3 += rel_w1 [(size_t)h * RELIN + DD + w]   * pred_emb[w];
    }
    for (int o = 16; o > 0; o >>= 1) {
        s1 += __shfl_down_sync(0xffffffffu, s1, o);
        s2 += __shfl_down_sync(0xffffffffu, s2, o);
        s3 += __shfl_down_sync(0xffffffffu, s3, o);
    }
    __shared__ float red[3][4];
    int wrp = t >> 5, lan = t & 31;
    if (lan == 0) { red[0][wrp] = s1; red[1][wrp] = s2; red[2][wrp] = s3; }
    __syncthreads();
    if (t == 0) {
        g_c_subj[h]  = red[0][0] + red[0][1] + red[0][2] + red[0][3] + subj_b1[h];
        g_c_obj[h]   = red[1][0] + red[1][1] + red[1][2] + red[1][3] + obj_b1[h];
        g_bias512[h] = red[2][0] + red[2][1] + red[2][2] + red[2][3] + rel_b1[h];
    }
    for (int d = t; d < DD; d += 128) {
        g_Wsum_s[h * DD + d] = fuse_s_w1[(size_t)h * (2*DD) + d] + fuse_s_w1[(size_t)h * (2*DD) + DD + d];
        g_Wsum_o[h * DD + d] = fuse_o_w1[(size_t)h * (2*DD) + d] + fuse_o_w1[(size_t)h * (2*DD) + DD + d];
    }
}

// ---------------- tiled NN GEMM: C = A(MxK) @ B(KxN) ----------------
template<bool F16OUT>
__global__ __launch_bounds__(256)
void nn_gemm_kernel(const float* __restrict__ A0, const float* __restrict__ B0,
                    float* __restrict__ C0, __half* __restrict__ Ch0,
                    const float* __restrict__ A1, const float* __restrict__ B1,
                    float* __restrict__ C1, __half* __restrict__ Ch1,
                    int N, int K, int lda, int ldb) {
    __shared__ float Ask[16][68];
    __shared__ float Bs [16][68];
    const int br = blockIdx.z;
    const float* A = br ? A1 : A0;
    const float* B = br ? B1 : B0;
    const int m0 = blockIdx.y * 64, n0 = blockIdx.x * 64;
    const int tid = threadIdx.x;
    const int tr = tid >> 4, tc = tid & 15;
    float acc[4][4];
    #pragma unroll
    for (int i = 0; i < 4; i++)
        #pragma unroll
        for (int j = 0; j < 4; j++) acc[i][j] = 0.f;

    for (int k0 = 0; k0 < K; k0 += 16) {
        {
            int r = tid >> 2, kq = (tid & 3) * 4;
            float4 v = *reinterpret_cast<const float4*>(&A[(size_t)(m0 + r) * lda + k0 + kq]);
            Ask[kq + 0][r] = v.x; Ask[kq + 1][r] = v.y;
            Ask[kq + 2][r] = v.z; Ask[kq + 3][r] = v.w;
        }
        {
            int k = tid >> 4, nq = (tid & 15) * 4;
            float4 v = *reinterpret_cast<const float4*>(&B[(size_t)(k0 + k) * ldb + n0 + nq]);
            *reinterpret_cast<float4*>(&Bs[k][nq]) = v;
        }
        __syncthreads();
        #pragma unroll
        for (int k = 0; k < 16; k++) {
            float a[4], b[4];
            *reinterpret_cast<float4*>(a) = *reinterpret_cast<const float4*>(&Ask[k][tr * 4]);
            *reinterpret_cast<float4*>(b) = *reinterpret_cast<const float4*>(&Bs[k][tc * 4]);
            #pragma unroll
            for (int i = 0; i < 4; i++)
                #pragma unroll
                for (int j = 0; j < 4; j++)
                    acc[i][j] = fmaf(a[i], b[j], acc[i][j]);
        }
        __syncthreads();
    }

    if (F16OUT) {
        __half* Ch = br ? Ch1 : Ch0;
        #pragma unroll
        for (int i = 0; i < 4; i++)
            #pragma unroll
            for (int j = 0; j < 4; j++) {
                size_t off = (size_t)(m0 + tr * 4 + i) * N + n0 + tc * 4 + j;
                Ch[off] = __float2half_rn(acc[i][j]);
            }
    } else {
        float* C = br ? C1 : C0;
        #pragma unroll
        for (int i = 0; i < 4; i++)
            #pragma unroll
            for (int j = 0; j < 4; j++)
                C[(size_t)(m0 + tr * 4 + i) * N + n0 + tc * 4 + j] = acc[i][j];
    }
}

// ---------------- batched small GEMV for bias folds ----------------
__global__ void gemv4_kernel(const float* __restrict__ subj_b2, const float* __restrict__ obj_b2,
                             const float* __restrict__ fuse_s_b1, const float* __restrict__ fuse_o_b1,
                             const float* __restrict__ fuse_s_b2, const float* __restrict__ fuse_o_b2) {
    int which = blockIdx.y;
    const float *A, *v, *add; float* o;
    if      (which == 0) { A = g_Wsum_s; v = subj_b2;  add = fuse_s_b1; o = g_bf_s; }
    else if (which == 1) { A = g_Wsum_o; v = obj_b2;   add = fuse_o_b1; o = g_bf_o; }
    else if (which == 2) { A = g_Wc_s;   v = fuse_s_b2; add = g_bias512; o = g_cvec_s; }
    else                 { A = g_Wc_o;   v = fuse_o_b2; add = nullptr;  o = g_cvec_o; }
    int h = blockIdx.x * 8 + (threadIdx.x >> 5);
    int lane = threadIdx.x & 31;
    float s = 0.f;
    for (int d = lane; d < DD; d += 32) s += A[h * DD + d] * v[d];
    #pragma unroll
    for (int off = 16; off > 0; off >>= 1) s += __shfl_down_sync(0xffffffffu, s, off);
    if (lane == 0) o[h] = s + (add ? add[h] : 0.f);
}

// ================= chain HMMA GEMM (fp16, cp.async double-buffered) ====
// planes per buffer: X (10240) | W (10240)
#define CPSTR   80
#define CBUFSZ  20480
#define CSMEM   (512 + 2 * CBUFSZ)   // 41472

template<bool RELU, bool F16OUT>
__global__ __launch_bounds__(256, 2)
void chain_hmma_kernel(const __half* __restrict__ X0, const __half* __restrict__ X1,
                       int ldx,
                       const __half* __restrict__ W0, const __half* __restrict__ W1,
                       const float* __restrict__ bias0, const float* __restrict__ bias1,
                       float* __restrict__ C0, float* __restrict__ C1,
                       __half* __restrict__ Co0, __half* __restrict__ Co1,
                       int N, int K) {
    extern __shared__ char smem[];
    const uint32_t su = smem_u32(smem);
    float* biasS = reinterpret_cast<float*>(smem);

    const int tid  = threadIdx.x;
    const int wid  = tid >> 5;
    const int lane = tid & 31;
    const int wm   = wid >> 1;
    const int wn   = wid & 1;
    const int n0   = blockIdx.x * 128;
    const int m0   = blockIdx.y * 128;
    const int br   = blockIdx.z;

    const __half* X = br ? X1 : X0;
    const __half* W = br ? W1 : W0;
    const float* bias = br ? bias1 : bias0;

    if (tid < 128) biasS[tid] = bias[n0 + tid];

    auto stage = [&](int k0, int b) {
        uint32_t base = su + 512 + (uint32_t)b * CBUFSZ;
        #pragma unroll
        for (int e = 0; e < 2; e++) {
            int idx = e * 256 + tid;
            int r = idx >> 2, q = idx & 3;
            cp16(base +         r * CPSTR + q * 16, X + (size_t)(m0 + r) * ldx + k0 + q * 8);
            cp16(base + 10240 + r * CPSTR + q * 16, W + (size_t)(n0 + r) * K + k0 + q * 8);
        }
    };

    const uint32_t h_off = (uint32_t)((lane & 15) * CPSTR + (lane >> 4) * 16);
    const uint32_t w_off = (uint32_t)(((lane & 7) + ((lane >> 4) << 3)) * CPSTR
                                      + ((lane >> 3) & 1) * 16);

    float acc[2][8][4];
    #pragma unroll
    for (int mb = 0; mb < 2; mb++)
        #pragma unroll
        for (int nb = 0; nb < 8; nb++)
            #pragma unroll
            for (int q = 0; q < 4; q++) acc[mb][nb][q] = 0.f;

    stage(0, 0); cp_commit();
    const int nk = K / 32;

    for (int c = 0; c < nk; c++) {
        cp_wait0();
        __syncthreads();
        if (c + 1 < nk) { stage((c + 1) * 32, (c + 1) & 1); cp_commit(); }

        const uint32_t base = su + 512 + (uint32_t)(c & 1) * CBUFSZ;
        #pragma unroll
        for (int ks = 0; ks < 2; ks++) {
            uint32_t a[2][4];
            const uint32_t hbase = base + wm * (32 * CPSTR) + ks * 32 + h_off;
            ldsm4(a[0], hbase);
            ldsm4(a[1], hbase + 16 * CPSTR);
            const uint32_t wbase = base + 10240 + wn * (64 * CPSTR) + ks * 32 + w_off;
            #pragma unroll
            for (int g = 0; g < 4; g++) {
                uint32_t b[4];
                ldsm4(b, wbase + g * (16 * CPSTR));
                mma_f16(acc[0][g * 2 + 0], a[0], b);
                mma_f16(acc[0][g * 2 + 1], a[0], b + 2);
                mma_f16(acc[1][g * 2 + 0], a[1], b);
                mma_f16(acc[1][g * 2 + 1], a[1], b + 2);
            }
        }
    }

    // ---- epilogue ----
    const int qr = lane >> 2, qc = (lane & 3) * 2;
    float* C = br ? C1 : C0;
    __half* Co = br ? Co1 : Co0;
    #pragma unroll
    for (int mb = 0; mb < 2; mb++) {
        int rA = m0 + wm * 32 + mb * 16 + qr;
        int rB = rA + 8;
        #pragma unroll
        for (int nb = 0; nb < 8; nb++) {
            int ln = qc + wn * 64 + nb * 8;
            int col = n0 + ln;
            float vA0 = acc[mb][nb][0] + biasS[ln];
            float vA1 = acc[mb][nb][1] + biasS[ln + 1];
            float vB0 = acc[mb][nb][2] + biasS[ln];
            float vB1 = acc[mb][nb][3] + biasS[ln + 1];
            if (RELU) {
                vA0 = fmaxf(vA0, 0.f); vA1 = fmaxf(vA1, 0.f);
                vB0 = fmaxf(vB0, 0.f); vB1 = fmaxf(vB1, 0.f);
            }
            if (F16OUT) {
                *reinterpret_cast<__half2*>(&Co[(size_t)rA * N + col]) = __floats2half2_rn(vA0, vA1);
                *reinterpret_cast<__half2*>(&Co[(size_t)rB * N + col]) = __floats2half2_rn(vB0, vB1);
            } else {
                *reinterpret_cast<float2*>(&C[(size_t)rA * N + col]) = make_float2(vA0, vA1);
                *reinterpret_cast<float2*>(&C[(size_t)rB * N + col]) = make_float2(vB0, vB1);
            }
        }
    }
}

// ================= HMMA pairwise kernel (fp16 A/B, cp.async pipelined) ======
// smem layout:
//  0      b2        512
//  512    H (fp16)  10240
//  10752  buf0 { A 2x64B=128 | B 64x64B=4096 | W 128x80B=10240 } = 14464
//  25216  buf1
#define PW_H     512
#define PW_BUF0  10752
#define PW_BUFSZ 14464
#define PSTR     80
#define PSMEM    (PW_BUF0 + 2 * PW_BUFSZ)   // 39680

__global__ __launch_bounds__(256, 2)
void pairwise_hmma_kernel(const float* __restrict__ b2v,
                          float* __restrict__ out) {
    extern __shared__ char smem[];
    const uint32_t su = smem_u32(smem);
    float* bs2 = reinterpret_cast<float*>(smem);

    const int tid  = threadIdx.x;
    const int wid  = tid >> 5;
    const int lane = tid & 31;
    const int wm   = wid >> 1;
    const int wn   = wid & 1;

    const int n0  = blockIdx.x * 128;
    const int ib2 = blockIdx.y * 2;
    const int t   = blockIdx.z;

    if (tid < 128) bs2[tid] = b2v[n0 + tid];

    const size_t arow0 = (size_t)(t * 64 + ib2) * HH;
    const size_t brow0 = (size_t)(t * 64) * HH;

    auto stage = [&](int k0, int b) {
        uint32_t base = su + PW_BUF0 + (uint32_t)b * PW_BUFSZ;
        if (tid < 8) {                             // A (fp16, bias folded): 2 rows x 32
            int r = tid >> 2, q = tid & 3;
            cp16(base + r * 64 + q * 16, g_A16 + arow0 + (size_t)r * HH + k0 + q * 8);
        }
        {                                          // B (fp16): 64 rows x 32, stride 64B
            int j = tid >> 2, q = tid & 3;
            cp16(base + 128 + j * 64 + q * 16, g_B16 + brow0 + (size_t)j * HH + k0 + q * 8);
        }
        #pragma unroll
        for (int e = 0; e < 2; e++) {              // W: 128 x 32 fp16, stride 80B
            int idx = e * 256 + tid;
            int n = idx >> 2, q = idx & 3;
            cp16(base + 4224 + n * PSTR + q * 16, g_W2 + (size_t)(n0 + n) * HH + k0 + q * 8);
        }
    };

    const uint32_t h_off = (uint32_t)((lane & 15) * PSTR + (lane >> 4) * 16);
    const uint32_t w_off = (uint32_t)(((lane & 7) + ((lane >> 4) << 3)) * PSTR
                                      + ((lane >> 3) & 1) * 16);

    float acc[2][8][4];
    #pragma unroll
    for (int mb = 0; mb < 2; mb++)
        #pragma unroll
        for (int nb = 0; nb < 8; nb++)
            #pragma unroll
            for (int q = 0; q < 4; q++) acc[mb][nb][q] = 0.f;

    stage(0, 0); cp_commit();
    const __half2 hz = __floats2half2_rn(0.f, 0.f);

    for (int c = 0; c < 16; c++) {
        cp_wait0();
        __syncthreads();                 // buf(c) ready; all mma(c-1) reads done
        if (c + 1 < 16) { stage((c + 1) * 32, (c + 1) & 1); cp_commit(); }

        const uint32_t bo = PW_BUF0 + (uint32_t)(c & 1) * PW_BUFSZ;
        const __half* AsB = reinterpret_cast<const __half*>(smem + bo);
        const __half* BsB = reinterpret_cast<const __half*>(smem + bo + 128);

        // ---- build H (128 x 32 fp16) = max(A - B, 0), pure fp16 ----
        #pragma unroll
        for (int e = 0; e < 8; e++) {
            int idx = e * 256 + tid;
            int p  = idx >> 4;
            int kp = idx & 15;
            int k  = kp * 2;
            int i  = p >> 6, j = p & 63;
            __half2 av = *reinterpret_cast<const __half2*>(&AsB[i * 32 + k]);
            __half2 bv = *reinterpret_cast<const __half2*>(&BsB[j * 32 + k]);
            __half2 h = __hmax2(__hsub2(av, bv), hz);
            *reinterpret_cast<__half2*>(smem + PW_H + p * PSTR + k * 2) = h;
        }
        __syncthreads();                 // H staged

        const uint32_t base = su + bo;
        #pragma unroll
        for (int ks = 0; ks < 2; ks++) {
            uint32_t a[2][4];
            const uint32_t hbase = su + PW_H + wm * (32 * PSTR) + ks * 32 + h_off;
            ldsm4(a[0], hbase);
            ldsm4(a[1], hbase + 16 * PSTR);
            const uint32_t wbase = base + 4224 + wn * (64 * PSTR) + ks * 32 + w_off;
            #pragma unroll
            for (int g = 0; g < 4; g++) {
                uint32_t b[4];
                ldsm4(b, wbase + g * (16 * PSTR));
                mma_f16(acc[0][g * 2 + 0], a[0], b);
                mma_f16(acc[0][g * 2 + 1], a[0], b + 2);
                mma_f16(acc[1][g * 2 + 0], a[1], b);
                mma_f16(acc[1][g * 2 + 1], a[1], b + 2);
            }
        }
    }

    const int qr = lane >> 2, qc = (lane & 3) * 2;
    #pragma unroll
    for (int mb = 0; mb < 2; mb++) {
        int rA = wm * 32 + mb * 16 + qr;
        int rB = rA + 8;
        float* oA = out + ((size_t)(t * 64 + ib2 + (rA >> 6)) * 64 + (rA & 63)) * 256
                        + n0 + wn * 64 + qc;
        float* oB = out + ((size_t)(t * 64 + ib2 + (rB >> 6)) * 64 + (rB & 63)) * 256
                        + n0 + wn * 64 + qc;
        #pragma unroll
        for (int nb = 0; nb < 8; nb++) {
            int ln = wn * 64 + nb * 8 + qc;
            float2 vA = make_float2(acc[mb][nb][0] + bs2[ln],
                                    acc[mb][nb][1] + bs2[ln + 1]);
            float2 vB = make_float2(acc[mb][nb][2] + bs2[ln],
                                    acc[mb][nb][3] + bs2[ln + 1]);
            *reinterpret_cast<float2*>(oA + nb * 8) = vA;
            *reinterpret_cast<float2*>(oB + nb * 8) = vB;
        }
    }
}

// ---------------- host launch ----------------
extern "C" void kernel_launch(void* const* d_in, const int* in_sizes, int n_in,
                              void* d_out, int out_size) {
    const float* roi       = (const float*)d_in[0];
    const float* spatial   = (const float*)d_in[1];
    const float* subj_emb  = (const float*)d_in[3];
    const float* obj_emb   = (const float*)d_in[4];
    const float* pred_emb  = (const float*)d_in[5];
    const float* subj_w1   = (const float*)d_in[6];
    const float* subj_b1   = (const float*)d_in[7];
    const float* subj_w2   = (const float*)d_in[8];
    const float* subj_b2   = (const float*)d_in[9];
    const float* obj_w1    = (const float*)d_in[10];
    const float* obj_b1    = (const float*)d_in[11];
    const float* obj_w2    = (const float*)d_in[12];
    const float* obj_b2    = (const float*)d_in[13];
    const float* fuse_s_w1 = (const float*)d_in[14];
    const float* fuse_s_b1 = (const float*)d_in[15];
    const float* fuse_s_w2 = (const float*)d_in[16];
    const float* fuse_s_b2 = (const float*)d_in[17];
    const float* fuse_o_w1 = (const float*)d_in[18];
    const float* fuse_o_b1 = (const float*)d_in[19];
    const float* fuse_o_w2 = (const float*)d_in[20];
    const float* fuse_o_b2 = (const float*)d_in[21];
    const float* W_rs      = (const float*)d_in[22];
    const float* W_ro      = (const float*)d_in[23];
    const float* rel_w1    = (const float*)d_in[24];
    const float* rel_b1    = (const float*)d_in[25];
    const float* rel_w2    = (const float*)d_in[26];
    const float* rel_b2    = (const float*)d_in[27];
    float* out = (float*)d_out;

    __half *pX16, *pW1_s, *pW1_o;
    __half *pY1_s, *pY1_o, *pY2_s, *pY2_o;
    __half *pWf_s, *pWf_o, *pWcc_s, *pWcc_o;
    __half *pA16, *pB16;
    float *pWsum_s, *pWsum_o, *pWc_s, *pWc_o;
    float *pc_subj, *pc_obj, *pbf_s, *pbf_o, *pcv_s, *pcv_o;
    cudaGetSymbolAddress((void**)&pX16, g_X16);
    cudaGetSymbolAddress((void**)&pW1_s, g_W1_s);
    cudaGetSymbolAddress((void**)&pW1_o, g_W1_o);
    cudaGetSymbolAddress((void**)&pY1_s, g_Y1_s);
    cudaGetSymbolAddress((void**)&pY1_o, g_Y1_o);
    cudaGetSymbolAddress((void**)&pY2_s, g_Y2_s);
    cudaGetSymbolAddress((void**)&pY2_o, g_Y2_o);
    cudaGetSymbolAddress((void**)&pWf_s, g_Wf_s);
    cudaGetSymbolAddress((void**)&pWf_o, g_Wf_o);
    cudaGetSymbolAddress((void**)&pWcc_s, g_Wcc_s);
    cudaGetSymbolAddress((void**)&pWcc_o, g_Wcc_o);
    cudaGetSymbolAddress((void**)&pA16, g_A16);
    cudaGetSymbolAddress((void**)&pB16, g_B16);
    cudaGetSymbolAddress((void**)&pWsum_s, g_Wsum_s);
    cudaGetSymbolAddress((void**)&pWsum_o, g_Wsum_o);
    cudaGetSymbolAddress((void**)&pWc_s, g_Wc_s);
    cudaGetSymbolAddress((void**)&pWc_o, g_Wc_o);
    cudaGetSymbolAddress((void**)&pc_subj, g_c_subj);
    cudaGetSymbolAddress((void**)&pc_obj,  g_c_obj);
    cudaGetSymbolAddress((void**)&pbf_s,  g_bf_s);
    cudaGetSymbolAddress((void**)&pbf_o,  g_bf_o);
    cudaGetSymbolAddress((void**)&pcv_s,  g_cvec_s);
    cudaGetSymbolAddress((void**)&pcv_o,  g_cvec_o);

    static bool attr_set = false;
    if (!attr_set) {
        cudaFuncSetAttribute(pairwise_hmma_kernel,
                             cudaFuncAttributeMaxDynamicSharedMemorySize, PSMEM);
        cudaFuncSetAttribute(chain_hmma_kernel<true, true>,
                             cudaFuncAttributeMaxDynamicSharedMemorySize, CSMEM);
        cudaFuncSetAttribute(chain_hmma_kernel<false, true>,
                             cudaFuncAttributeMaxDynamicSharedMemorySize, CSMEM);
        attr_set = true;
    }

    // 1. pack + precompute
    pack_x_kernel<<<NROWS, 256>>>(roi, spatial);
    split_w1_kernel<<<(HH * KP1 + 255) / 256, 256>>>(subj_w1, obj_w1);
    split_w2_kernel<<<512, 256>>>(rel_w2);
    pre_vec_kernel<<<HH, 128>>>(subj_w1, subj_b1, obj_w1, obj_b1, rel_w1, rel_b1,
                                subj_emb, obj_emb, pred_emb, fuse_s_w1, fuse_o_w1);
    nn_gemm_kernel<false><<<dim3(4, 8, 2), 256>>>(
        rel_w1, W_rs, pWc_s, nullptr,
        rel_w1, W_ro, pWc_o, nullptr,
        DD, DD, RELIN, DD);
    nn_gemm_kernel<true><<<dim3(8, 8, 2), 256>>>(
        pWsum_s, subj_w2, nullptr, pWf_s,
        pWsum_o, obj_w2,  nullptr, pWf_o,
        HH, DD, DD, HH);
    nn_gemm_kernel<true><<<dim3(8, 8, 2), 256>>>(
        pWc_s, fuse_s_w2, nullptr, pWcc_s,
        pWc_o, fuse_o_w2, nullptr, pWcc_o,
        HH, DD, DD, HH);
    gemv4_kernel<<<dim3(64, 4), 256>>>(subj_b2, obj_b2, fuse_s_b1, fuse_o_b1,
                                       fuse_s_b2, fuse_o_b2);

    dim3 cgrid(HH / 128, NROWS / 128, 2);

    // 2. layer 1: relu(X @ W1^T + c) -> Y1 fp16
    chain_hmma_kernel<true, true><<<cgrid, 256, CSMEM>>>(
        pX16, pX16, KP1,
        pW1_s, pW1_o,
        pc_subj, pc_obj,
        nullptr, nullptr,
        pY1_s, pY1_o,
        HH, KP1);

    // 3. layer 2: relu(Y1 @ Wf^T + bf) -> Y2 fp16
    chain_hmma_kernel<true, true><<<cgrid, 256, CSMEM>>>(
        pY1_s, pY1_o, HH,
        pWf_s, pWf_o,
        pbf_s, pbf_o,
        nullptr, nullptr,
        pY2_s, pY2_o,
        HH, HH);

    // 4. layer 3: Y2 @ Wcc^T + cvec(+bias512 for A) -> A/B fp16
    chain_hmma_kernel<false, true><<<cgrid, 256, CSMEM>>>(
        pY2_s, pY2_o, HH,
        pWcc_s, pWcc_o,
        pcv_s, pcv_o,
        nullptr, nullptr,
        pA16, pB16,
        HH, HH);

    // 5. pairwise GEMM (HMMA fp16 A/B, pipelined)
    pairwise_hmma_kernel<<<dim3(2, 32, 64), 256, PSMEM>>>(rel_b2, out);

    (void)in_sizes; (void)n_in; (void)out_size;
}

// round 15
// speedup vs baseline: 1.1366x; 1.0477x over previous
#include <cuda_runtime.h>
#include <cuda_bf16.h>
#include <cuda_fp16.h>
#include <cstdint>
#include <cstddef>

// ---------------- problem constants ----------------
#define TT      64
#define MM      64
#define NROWS   4096      // T*M
#define ROI     2048
#define SPA     4
#define WORD    300
#define ROISPA  2052      // ROI+SPA
#define INW     2352      // ROI+SPA+WORD
#define HH      512
#define DD      256
#define RELIN   556       // D + WORD
#define KP1     2080      // ROISPA padded to 65*32

// ---------------- scratch (device globals; no allocation) ----------------
__device__ __half g_X16 [NROWS * KP1];                      // activations fp16
__device__ __half g_W1_s[HH * KP1], g_W1_o[HH * KP1];       // weights fp16
__device__ __half g_Y1_s[NROWS * HH], g_Y1_o[NROWS * HH];
__device__ __half g_Y2_s[NROWS * HH], g_Y2_o[NROWS * HH];
__device__ __half g_Wf_s[HH * HH], g_Wf_o[HH * HH];
__device__ __half g_Wcc_s[HH * HH], g_Wcc_o[HH * HH];
__device__ __half g_A16[NROWS * HH];   // A + bias512 folded, fp16
__device__ __half g_B16[NROWS * HH];   // B, fp16
__device__ float g_Wsum_s[HH * DD], g_Wsum_o[HH * DD];
__device__ float g_Wc_s  [HH * DD], g_Wc_o  [HH * DD];
__device__ float g_c_subj[HH], g_c_obj[HH], g_bias512[HH];
__device__ float g_bf_s[HH], g_bf_o[HH], g_cvec_s[HH], g_cvec_o[HH];
__device__ __half g_W2[DD * HH];

// ---------------- helpers ----------------
__device__ __forceinline__ uint32_t smem_u32(const void* p) {
    uint32_t a;
    asm("{ .reg .u64 t; cvta.to.shared.u64 t, %1; cvt.u32.u64 %0, t; }"
        : "=r"(a) : "l"(p));
    return a;
}
__device__ __forceinline__ void ldsm4(uint32_t* r, uint32_t addr) {
    asm volatile("ldmatrix.sync.aligned.m8n8.x4.shared.b16 {%0,%1,%2,%3}, [%4];"
        : "=r"(r[0]), "=r"(r[1]), "=r"(r[2]), "=r"(r[3]) : "r"(addr));
}
__device__ __forceinline__ void mma_f16(float* c, const uint32_t* a, const uint32_t* b) {
    asm volatile(
        "mma.sync.aligned.m16n8k16.row.col.f32.f16.f16.f32 "
        "{%0,%1,%2,%3}, {%4,%5,%6,%7}, {%8,%9}, {%0,%1,%2,%3};"
        : "+f"(c[0]), "+f"(c[1]), "+f"(c[2]), "+f"(c[3])
        : "r"(a[0]), "r"(a[1]), "r"(a[2]), "r"(a[3]), "r"(b[0]), "r"(b[1]));
}
__device__ __forceinline__ void cp16(uint32_t dst, const void* src) {
    asm volatile("cp.async.ca.shared.global [%0], [%1], 16;" :: "r"(dst), "l"(src));
}
__device__ __forceinline__ void cp_commit() {
    asm volatile("cp.async.commit_group;");
}
__device__ __forceinline__ void cp_wait0() {
    asm volatile("cp.async.wait_group 0;" ::: "memory");
}

// ---------------- merged conversions: pack X | W1->fp16 | W2->fp16 ----------------
#define CV_W1BLKS (HH * KP1 / 256)        // 4160
#define CV_W2BLKS (DD * HH / 256)         // 512
#define CV_BLOCKS (NROWS + CV_W1BLKS + CV_W2BLKS)   // 8768

__global__ void convert_all_kernel(const float* __restrict__ roi,
                                   const float* __restrict__ spa,
                                   const float* __restrict__ s_w1,
                                   const float* __restrict__ o_w1,
                                   const float* __restrict__ w2) {
    int b = blockIdx.x;
    if (b < NROWS) {
        int r = b;
        for (int k = threadIdx.x; k < KP1; k += 256) {
            float v = 0.f;
            if (k < ROI)         v = roi[(size_t)r * ROI + k];
            else if (k < ROISPA) v = spa[(size_t)r * SPA + (k - ROI)];
            g_X16[(size_t)r * KP1 + k] = __float2half_rn(v);
        }
    } else if (b < NROWS + CV_W1BLKS) {
        int idx = (b - NROWS) * 256 + threadIdx.x;
        int n = idx / KP1, k = idx - n * KP1;
        float vs = (k < ROISPA) ? s_w1[(size_t)n * INW + k] : 0.f;
        float vo = (k < ROISPA) ? o_w1[(size_t)n * INW + k] : 0.f;
        g_W1_s[idx] = __float2half_rn(vs);
        g_W1_o[idx] = __float2half_rn(vo);
    } else {
        int idx = (b - NROWS - CV_W1BLKS) * 256 + threadIdx.x;
        g_W2[idx] = __float2half_rn(w2[idx]);
    }
}

// ---------------- constant biases + Wsum ----------------
__global__ void pre_vec_kernel(const float* __restrict__ subj_w1, const float* __restrict__ subj_b1,
                               const float* __restrict__ obj_w1,  const float* __restrict__ obj_b1,
                               const float* __restrict__ rel_w1,  const float* __restrict__ rel_b1,
                               const float* __restrict__ subj_emb, const float* __restrict__ obj_emb,
                               const float* __restrict__ pred_emb,
                               const float* __restrict__ fuse_s_w1, const float* __restrict__ fuse_o_w1) {
    int h = blockIdx.x;
    int t = threadIdx.x;
    float s1 = 0.f, s2 = 0.f, s3 = 0.f;
    for (int w = t; w < WORD; w += 128) {
        s1 += subj_w1[(size_t)h * INW + ROISPA + w] * subj_emb[w];
        s2 += obj_w1 [(size_t)h * INW + ROISPA + w] * obj_emb[w];
        s3 += rel_w1 [(size_t)h * RELIN + DD + w]   * pred_emb[w];
    }
    for (int o = 16; o > 0; o >>= 1) {
        s1 += __shfl_down_sync(0xffffffffu, s1, o);
        s2 += __shfl_down_sync(0xffffffffu, s2, o);
        s3 += __shfl_down_sync(0xffffffffu, s3, o);
    }
    __shared__ float red[3][4];
    int wrp = t >> 5, lan = t & 31;
    if (lan == 0) { red[0][wrp] = s1; red[1][wrp] = s2; red[2][wrp] = s3; }
    __syncthreads();
    if (t == 0) {
        g_c_subj[h]  = red[0][0] + red[0][1] + red[0][2] + red[0][3] + subj_b1[h];
        g_c_obj[h]   = red[1][0] + red[1][1] + red[1][2] + red[1][3] + obj_b1[h];
        g_bias512[h] = red[2][0] + red[2][1] + red[2][2] + red[2][3] + rel_b1[h];
    }
    for (int d = t; d < DD; d += 128) {
        g_Wsum_s[h * DD + d] = fuse_s_w1[(size_t)h * (2*DD) + d] + fuse_s_w1[(size_t)h * (2*DD) + DD + d];
        g_Wsum_o[h * DD + d] = fuse_o_w1[(size_t)h * (2*DD) + d] + fuse_o_w1[(size_t)h * (2*DD) + DD + d];
    }
}

// ---------------- tiled NN GEMM: C = A(MxK) @ B(KxN) ----------------
template<bool F16OUT>
__global__ __launch_bounds__(256)
void nn_gemm_kernel(const float* __restrict__ A0, const float* __restrict__ B0,
                    float* __restrict__ C0, __half* __restrict__ Ch0,
                    const float* __restrict__ A1, const float* __restrict__ B1,
                    float* __restrict__ C1, __half* __restrict__ Ch1,
                    int N, int K, int lda, int ldb) {
    __shared__ float Ask[16][68];
    __shared__ float Bs [16][68];
    const int br = blockIdx.z;
    const float* A = br ? A1 : A0;
    const float* B = br ? B1 : B0;
    const int m0 = blockIdx.y * 64, n0 = blockIdx.x * 64;
    const int tid = threadIdx.x;
    const int tr = tid >> 4, tc = tid & 15;
    float acc[4][4];
    #pragma unroll
    for (int i = 0; i < 4; i++)
        #pragma unroll
        for (int j = 0; j < 4; j++) acc[i][j] = 0.f;

    for (int k0 = 0; k0 < K; k0 += 16) {
        {
            int r = tid >> 2, kq = (tid & 3) * 4;
            float4 v = *reinterpret_cast<const float4*>(&A[(size_t)(m0 + r) * lda + k0 + kq]);
            Ask[kq + 0][r] = v.x; Ask[kq + 1][r] = v.y;
            Ask[kq + 2][r] = v.z; Ask[kq + 3][r] = v.w;
        }
        {
            int k = tid >> 4, nq = (tid & 15) * 4;
            float4 v = *reinterpret_cast<const float4*>(&B[(size_t)(k0 + k) * ldb + n0 + nq]);
            *reinterpret_cast<float4*>(&Bs[k][nq]) = v;
        }
        __syncthreads();
        #pragma unroll
        for (int k = 0; k < 16; k++) {
            float a[4], b[4];
            *reinterpret_cast<float4*>(a) = *reinterpret_cast<const float4*>(&Ask[k][tr * 4]);
            *reinterpret_cast<float4*>(b) = *reinterpret_cast<const float4*>(&Bs[k][tc * 4]);
            #pragma unroll
            for (int i = 0; i < 4; i++)
                #pragma unroll
                for (int j = 0; j < 4; j++)
                    acc[i][j] = fmaf(a[i], b[j], acc[i][j]);
        }
        __syncthreads();
    }

    if (F16OUT) {
        __half* Ch = br ? Ch1 : Ch0;
        #pragma unroll
        for (int i = 0; i < 4; i++)
            #pragma unroll
            for (int j = 0; j < 4; j++) {
                size_t off = (size_t)(m0 + tr * 4 + i) * N + n0 + tc * 4 + j;
                Ch[off] = __float2half_rn(acc[i][j]);
            }
    } else {
        float* C = br ? C1 : C0;
        #pragma unroll
        for (int i = 0; i < 4; i++)
            #pragma unroll
            for (int j = 0; j < 4; j++)
                C[(size_t)(m0 + tr * 4 + i) * N + n0 + tc * 4 + j] = acc[i][j];
    }
}

// ---------------- batched small GEMV for bias folds ----------------
__global__ void gemv4_kernel(const float* __restrict__ subj_b2, const float* __restrict__ obj_b2,
                             const float* __restrict__ fuse_s_b1, const float* __restrict__ fuse_o_b1,
                             const float* __restrict__ fuse_s_b2, const float* __restrict__ fuse_o_b2) {
    int which = blockIdx.y;
    const float *A, *v, *add; float* o;
    if      (which == 0) { A = g_Wsum_s; v = subj_b2;  add = fuse_s_b1; o = g_bf_s; }
    else if (which == 1) { A = g_Wsum_o; v = obj_b2;   add = fuse_o_b1; o = g_bf_o; }
    else if (which == 2) { A = g_Wc_s;   v = fuse_s_b2; add = g_bias512; o = g_cvec_s; }
    else                 { A = g_Wc_o;   v = fuse_o_b2; add = nullptr;  o = g_cvec_o; }
    int h = blockIdx.x * 8 + (threadIdx.x >> 5);
    int lane = threadIdx.x & 31;
    float s = 0.f;
    for (int d = lane; d < DD; d += 32) s += A[h * DD + d] * v[d];
    #pragma unroll
    for (int off = 16; off > 0; off >>= 1) s += __shfl_down_sync(0xffffffffu, s, off);
    if (lane == 0) o[h] = s + (add ? add[h] : 0.f);
}

// ================= chain HMMA GEMM (fp16, cp.async double-buffered) ====
#define CPSTR   80
#define CBUFSZ  20480
#define CSMEM   (512 + 2 * CBUFSZ)   // 41472

template<bool RELU, bool F16OUT>
__global__ __launch_bounds__(256, 2)
void chain_hmma_kernel(const __half* __restrict__ X0, const __half* __restrict__ X1,
                       int ldx,
                       const __half* __restrict__ W0, const __half* __restrict__ W1,
                       const float* __restrict__ bias0, const float* __restrict__ bias1,
                       float* __restrict__ C0, float* __restrict__ C1,
                       __half* __restrict__ Co0, __half* __restrict__ Co1,
                       int N, int K) {
    extern __shared__ char smem[];
    const uint32_t su = smem_u32(smem);
    float* biasS = reinterpret_cast<float*>(smem);

    const int tid  = threadIdx.x;
    const int wid  = tid >> 5;
    const int lane = tid & 31;
    const int wm   = wid >> 1;
    const int wn   = wid & 1;
    const int n0   = blockIdx.x * 128;
    const int m0   = blockIdx.y * 128;
    const int br   = blockIdx.z;

    const __half* X = br ? X1 : X0;
    const __half* W = br ? W1 : W0;
    const float* bias = br ? bias1 : bias0;

    if (tid < 128) biasS[tid] = bias[n0 + tid];

    auto stage = [&](int k0, int b) {
        uint32_t base = su + 512 + (uint32_t)b * CBUFSZ;
        #pragma unroll
        for (int e = 0; e < 2; e++) {
            int idx = e * 256 + tid;
            int r = idx >> 2, q = idx & 3;
            cp16(base +         r * CPSTR + q * 16, X + (size_t)(m0 + r) * ldx + k0 + q * 8);
            cp16(base + 10240 + r * CPSTR + q * 16, W + (size_t)(n0 + r) * K + k0 + q * 8);
        }
    };

    const uint32_t h_off = (uint32_t)((lane & 15) * CPSTR + (lane >> 4) * 16);
    const uint32_t w_off = (uint32_t)(((lane & 7) + ((lane >> 4) << 3)) * CPSTR
                                      + ((lane >> 3) & 1) * 16);

    float acc[2][8][4];
    #pragma unroll
    for (int mb = 0; mb < 2; mb++)
        #pragma unroll
        for (int nb = 0; nb < 8; nb++)
            #pragma unroll
            for (int q = 0; q < 4; q++) acc[mb][nb][q] = 0.f;

    stage(0, 0); cp_commit();
    const int nk = K / 32;

    for (int c = 0; c < nk; c++) {
        cp_wait0();
        __syncthreads();
        if (c + 1 < nk) { stage((c + 1) * 32, (c + 1) & 1); cp_commit(); }

        const uint32_t base = su + 512 + (uint32_t)(c & 1) * CBUFSZ;
        #pragma unroll
        for (int ks = 0; ks < 2; ks++) {
            uint32_t a[2][4];
            const uint32_t hbase = base + wm * (32 * CPSTR) + ks * 32 + h_off;
            ldsm4(a[0], hbase);
            ldsm4(a[1], hbase + 16 * CPSTR);
            const uint32_t wbase = base + 10240 + wn * (64 * CPSTR) + ks * 32 + w_off;
            #pragma unroll
            for (int g = 0; g < 4; g++) {
                uint32_t b[4];
                ldsm4(b, wbase + g * (16 * CPSTR));
                mma_f16(acc[0][g * 2 + 0], a[0], b);
                mma_f16(acc[0][g * 2 + 1], a[0], b + 2);
                mma_f16(acc[1][g * 2 + 0], a[1], b);
                mma_f16(acc[1][g * 2 + 1], a[1], b + 2);
            }
        }
    }

    // ---- epilogue ----
    const int qr = lane >> 2, qc = (lane & 3) * 2;
    float* C = br ? C1 : C0;
    __half* Co = br ? Co1 : Co0;
    #pragma unroll
    for (int mb = 0; mb < 2; mb++) {
        int rA = m0 + wm * 32 + mb * 16 + qr;
        int rB = rA + 8;
        #pragma unroll
        for (int nb = 0; nb < 8; nb++) {
            int ln = qc + wn * 64 + nb * 8;
            int col = n0 + ln;
            float vA0 = acc[mb][nb][0] + biasS[ln];
            float vA1 = acc[mb][nb][1] + biasS[ln + 1];
            float vB0 = acc[mb][nb][2] + biasS[ln];
            float vB1 = acc[mb][nb][3] + biasS[ln + 1];
            if (RELU) {
                vA0 = fmaxf(vA0, 0.f); vA1 = fmaxf(vA1, 0.f);
                vB0 = fmaxf(vB0, 0.f); vB1 = fmaxf(vB1, 0.f);
            }
            if (F16OUT) {
                *reinterpret_cast<__half2*>(&Co[(size_t)rA * N + col]) = __floats2half2_rn(vA0, vA1);
                *reinterpret_cast<__half2*>(&Co[(size_t)rB * N + col]) = __floats2half2_rn(vB0, vB1);
            } else {
                *reinterpret_cast<float2*>(&C[(size_t)rA * N + col]) = make_float2(vA0, vA1);
                *reinterpret_cast<float2*>(&C[(size_t)rB * N + col]) = make_float2(vB0, vB1);
            }
        }
    }
}

// ================= HMMA pairwise kernel (fp16 A/B, cp.async pipelined) ======
#define PW_H     512
#define PW_BUF0  10752
#define PW_BUFSZ 14464
#define PSTR     80
#define PSMEM    (PW_BUF0 + 2 * PW_BUFSZ)   // 39680

__global__ __launch_bounds__(256, 2)
void pairwise_hmma_kernel(const float* __restrict__ b2v,
                          float* __restrict__ out) {
    extern __shared__ char smem[];
    const uint32_t su = smem_u32(smem);
    float* bs2 = reinterpret_cast<float*>(smem);

    const int tid  = threadIdx.x;
    const int wid  = tid >> 5;
    const int lane = tid & 31;
    const int wm   = wid >> 1;
    const int wn   = wid & 1;

    const int n0  = blockIdx.x * 128;
    const int ib2 = blockIdx.y * 2;
    const int t   = blockIdx.z;

    if (tid < 128) bs2[tid] = b2v[n0 + tid];

    const size_t arow0 = (size_t)(t * 64 + ib2) * HH;
    const size_t brow0 = (size_t)(t * 64) * HH;

    auto stage = [&](int k0, int b) {
        uint32_t base = su + PW_BUF0 + (uint32_t)b * PW_BUFSZ;
        if (tid < 8) {
            int r = tid >> 2, q = tid & 3;
            cp16(base + r * 64 + q * 16, g_A16 + arow0 + (size_t)r * HH + k0 + q * 8);
        }
        {
            int j = tid >> 2, q = tid & 3;
            cp16(base + 128 + j * 64 + q * 16, g_B16 + brow0 + (size_t)j * HH + k0 + q * 8);
        }
        #pragma unroll
        for (int e = 0; e < 2; e++) {
            int idx = e * 256 + tid;
            int n = idx >> 2, q = idx & 3;
            cp16(base + 4224 + n * PSTR + q * 16, g_W2 + (size_t)(n0 + n) * HH + k0 + q * 8);
        }
    };

    const uint32_t h_off = (uint32_t)((lane & 15) * PSTR + (lane >> 4) * 16);
    const uint32_t w_off = (uint32_t)(((lane & 7) + ((lane >> 4) << 3)) * PSTR
                                      + ((lane >> 3) & 1) * 16);

    float acc[2][8][4];
    #pragma unroll
    for (int mb = 0; mb < 2; mb++)
        #pragma unroll
        for (int nb = 0; nb < 8; nb++)
            #pragma unroll
            for (int q = 0; q < 4; q++) acc[mb][nb][q] = 0.f;

    stage(0, 0); cp_commit();
    const __half2 hz = __floats2half2_rn(0.f, 0.f);

    for (int c = 0; c < 16; c++) {
        cp_wait0();
        __syncthreads();
        if (c + 1 < 16) { stage((c + 1) * 32, (c + 1) & 1); cp_commit(); }

        const uint32_t bo = PW_BUF0 + (uint32_t)(c & 1) * PW_BUFSZ;
        const __half* AsB = reinterpret_cast<const __half*>(smem + bo);
        const __half* BsB = reinterpret_cast<const __half*>(smem + bo + 128);

        #pragma unroll
        for (int e = 0; e < 8; e++) {
            int idx = e * 256 + tid;
            int p  = idx >> 4;
            int kp = idx & 15;
            int k  = kp * 2;
            int i  = p >> 6, j = p & 63;
            __half2 av = *reinterpret_cast<const __half2*>(&AsB[i * 32 + k]);
            __half2 bv = *reinterpret_cast<const __half2*>(&BsB[j * 32 + k]);
            __half2 h = __hmax2(__hsub2(av, bv), hz);
            *reinterpret_cast<__half2*>(smem + PW_H + p * PSTR + k * 2) = h;
        }
        __syncthreads();

        const uint32_t base = su + bo;
        #pragma unroll
        for (int ks = 0; ks < 2; ks++) {
            uint32_t a[2][4];
            const uint32_t hbase = su + PW_H + wm * (32 * PSTR) + ks * 32 + h_off;
            ldsm4(a[0], hbase);
            ldsm4(a[1], hbase + 16 * PSTR);
            const uint32_t wbase = base + 4224 + wn * (64 * PSTR) + ks * 32 + w_off;
            #pragma unroll
            for (int g = 0; g < 4; g++) {
                uint32_t b[4];
                ldsm4(b, wbase + g * (16 * PSTR));
                mma_f16(acc[0][g * 2 + 0], a[0], b);
                mma_f16(acc[0][g * 2 + 1], a[0], b + 2);
                mma_f16(acc[1][g * 2 + 0], a[1], b);
                mma_f16(acc[1][g * 2 + 1], a[1], b + 2);
            }
        }
    }

    const int qr = lane >> 2, qc = (lane & 3) * 2;
    #pragma unroll
    for (int mb = 0; mb < 2; mb++) {
        int rA = wm * 32 + mb * 16 + qr;
        int rB = rA + 8;
        float* oA = out + ((size_t)(t * 64 + ib2 + (rA >> 6)) * 64 + (rA & 63)) * 256
                        + n0 + wn * 64 + qc;
        float* oB = out + ((size_t)(t * 64 + ib2 + (rB >> 6)) * 64 + (rB & 63)) * 256
                        + n0 + wn * 64 + qc;
        #pragma unroll
        for (int nb = 0; nb < 8; nb++) {
            int ln = wn * 64 + nb * 8 + qc;
            float2 vA = make_float2(acc[mb][nb][0] + bs2[ln],
                                    acc[mb][nb][1] + bs2[ln + 1]);
            float2 vB = make_float2(acc[mb][nb][2] + bs2[ln],
                                    acc[mb][nb][3] + bs2[ln + 1]);
            *reinterpret_cast<float2*>(oA + nb * 8) = vA;
            *reinterpret_cast<float2*>(oB + nb * 8) = vB;
        }
    }
}

// ---------------- host launch ----------------
extern "C" void kernel_launch(void* const* d_in, const int* in_sizes, int n_in,
                              void* d_out, int out_size) {
    const float* roi       = (const float*)d_in[0];
    const float* spatial   = (const float*)d_in[1];
    const float* subj_emb  = (const float*)d_in[3];
    const float* obj_emb   = (const float*)d_in[4];
    const float* pred_emb  = (const float*)d_in[5];
    const float* subj_w1   = (const float*)d_in[6];
    const float* subj_b1   = (const float*)d_in[7];
    const float* subj_w2   = (const float*)d_in[8];
    const float* subj_b2   = (const float*)d_in[9];
    const float* obj_w1    = (const float*)d_in[10];
    const float* obj_b1    = (const float*)d_in[11];
    const float* obj_w2    = (const float*)d_in[12];
    const float* obj_b2    = (const float*)d_in[13];
    const float* fuse_s_w1 = (const float*)d_in[14];
    const float* fuse_s_b1 = (const float*)d_in[15];
    const float* fuse_s_w2 = (const float*)d_in[16];
    const float* fuse_s_b2 = (const float*)d_in[17];
    const float* fuse_o_w1 = (const float*)d_in[18];
    const float* fuse_o_b1 = (const float*)d_in[19];
    const float* fuse_o_w2 = (const float*)d_in[20];
    const float* fuse_o_b2 = (const float*)d_in[21];
    const float* W_rs      = (const float*)d_in[22];
    const float* W_ro      = (const float*)d_in[23];
    const float* rel_w1    = (const float*)d_in[24];
    const float* rel_b1    = (const float*)d_in[25];
    const float* rel_w2    = (const float*)d_in[26];
    const float* rel_b2    = (const float*)d_in[27];
    float* out = (float*)d_out;

    __half *pX16, *pW1_s, *pW1_o;
    __half *pY1_s, *pY1_o, *pY2_s, *pY2_o;
    __half *pWf_s, *pWf_o, *pWcc_s, *pWcc_o;
    __half *pA16, *pB16;
    float *pWsum_s, *pWsum_o, *pWc_s, *pWc_o;
    float *pc_subj, *pc_obj, *pbf_s, *pbf_o, *pcv_s, *pcv_o;
    cudaGetSymbolAddress((void**)&pX16, g_X16);
    cudaGetSymbolAddress((void**)&pW1_s, g_W1_s);
    cudaGetSymbolAddress((void**)&pW1_o, g_W1_o);
    cudaGetSymbolAddress((void**)&pY1_s, g_Y1_s);
    cudaGetSymbolAddress((void**)&pY1_o, g_Y1_o);
    cudaGetSymbolAddress((void**)&pY2_s, g_Y2_s);
    cudaGetSymbolAddress((void**)&pY2_o, g_Y2_o);
    cudaGetSymbolAddress((void**)&pWf_s, g_Wf_s);
    cudaGetSymbolAddress((void**)&pWf_o, g_Wf_o);
    cudaGetSymbolAddress((void**)&pWcc_s, g_Wcc_s);
    cudaGetSymbolAddress((void**)&pWcc_o, g_Wcc_o);
    cudaGetSymbolAddress((void**)&pA16, g_A16);
    cudaGetSymbolAddress((void**)&pB16, g_B16);
    cudaGetSymbolAddress((void**)&pWsum_s, g_Wsum_s);
    cudaGetSymbolAddress((void**)&pWsum_o, g_Wsum_o);
    cudaGetSymbolAddress((void**)&pWc_s, g_Wc_s);
    cudaGetSymbolAddress((void**)&pWc_o, g_Wc_o);
    cudaGetSymbolAddress((void**)&pc_subj, g_c_subj);
    cudaGetSymbolAddress((void**)&pc_obj,  g_c_obj);
    cudaGetSymbolAddress((void**)&pbf_s,  g_bf_s);
    cudaGetSymbolAddress((void**)&pbf_o,  g_bf_o);
    cudaGetSymbolAddress((void**)&pcv_s,  g_cvec_s);
    cudaGetSymbolAddress((void**)&pcv_o,  g_cvec_o);

    static bool init_done = false;
    static cudaStream_t s2 = nullptr;
    static cudaEvent_t e1 = nullptr, e_pv = nullptr, e2 = nullptr;
    if (!init_done) {
        cudaFuncSetAttribute(pairwise_hmma_kernel,
                             cudaFuncAttributeMaxDynamicSharedMemorySize, PSMEM);
        cudaFuncSetAttribute(chain_hmma_kernel<true, true>,
                             cudaFuncAttributeMaxDynamicSharedMemorySize, CSMEM);
        cudaFuncSetAttribute(chain_hmma_kernel<false, true>,
                             cudaFuncAttributeMaxDynamicSharedMemorySize, CSMEM);
        cudaStreamCreateWithFlags(&s2, cudaStreamNonBlocking);
        cudaEventCreateWithFlags(&e1,  cudaEventDisableTiming);
        cudaEventCreateWithFlags(&e_pv, cudaEventDisableTiming);
        cudaEventCreateWithFlags(&e2,  cudaEventDisableTiming);
        init_done = true;
    }

    // ---- fork: weight-prep branch on s2 (independent of X16/W1/W2 conversion) ----
    cudaEventRecord(e1, 0);
    cudaStreamWaitEvent(s2, e1, 0);

    pre_vec_kernel<<<HH, 128, 0, s2>>>(subj_w1, subj_b1, obj_w1, obj_b1, rel_w1, rel_b1,
                                       subj_emb, obj_emb, pred_emb, fuse_s_w1, fuse_o_w1);
    cudaEventRecord(e_pv, s2);          // c_subj/c_obj/bias512/Wsum ready
    nn_gemm_kernel<false><<<dim3(4, 8, 2), 256, 0, s2>>>(
        rel_w1, W_rs, pWc_s, nullptr,
        rel_w1, W_ro, pWc_o, nullptr,
        DD, DD, RELIN, DD);
    nn_gemm_kernel<true><<<dim3(8, 8, 2), 256, 0, s2>>>(
        pWsum_s, subj_w2, nullptr, pWf_s,
        pWsum_o, obj_w2,  nullptr, pWf_o,
        HH, DD, DD, HH);
    nn_gemm_kernel<true><<<dim3(8, 8, 2), 256, 0, s2>>>(
        pWc_s, fuse_s_w2, nullptr, pWcc_s,
        pWc_o, fuse_o_w2, nullptr, pWcc_o,
        HH, DD, DD, HH);
    gemv4_kernel<<<dim3(64, 4), 256, 0, s2>>>(subj_b2, obj_b2, fuse_s_b1, fuse_o_b1,
                                              fuse_s_b2, fuse_o_b2);
    cudaEventRecord(e2, s2);            // Wf/Wcc/bf/cvec ready

    // ---- main stream: conversions then chain ----
    convert_all_kernel<<<CV_BLOCKS, 256>>>(roi, spatial, subj_w1, obj_w1, rel_w2);

    dim3 cgrid(HH / 128, NROWS / 128, 2);

    cudaStreamWaitEvent(0, e_pv, 0);    // L1 bias dep
    chain_hmma_kernel<true, true><<<cgrid, 256, CSMEM>>>(
        pX16, pX16, KP1,
        pW1_s, pW1_o,
        pc_subj, pc_obj,
        nullptr, nullptr,
        pY1_s, pY1_o,
        HH, KP1);

    cudaStreamWaitEvent(0, e2, 0);      // L2/L3 weight deps
    chain_hmma_kernel<true, true><<<cgrid, 256, CSMEM>>>(
        pY1_s, pY1_o, HH,
        pWf_s, pWf_o,
        pbf_s, pbf_o,
        nullptr, nullptr,
        pY2_s, pY2_o,
        HH, HH);

    chain_hmma_kernel<false, true><<<cgrid, 256, CSMEM>>>(
        pY2_s, pY2_o, HH,
        pWcc_s, pWcc_o,
        pcv_s, pcv_o,
        nullptr, nullptr,
        pA16, pB16,
        HH, HH);

    // pairwise GEMM (HMMA fp16 A/B, pipelined)
    pairwise_hmma_kernel<<<dim3(2, 32, 64), 256, PSMEM>>>(rel_b2, out);

    (void)in_sizes; (void)n_in; (void)out_size;
}

// round 16
// speedup vs baseline: 1.2202x; 1.0735x over previous
#include <cuda_runtime.h>
#include <cuda_bf16.h>
#include <cuda_fp16.h>
#include <cstdint>
#include <cstddef>

// ---------------- problem constants ----------------
#define TT      64
#define MM      64
#define NROWS   4096      // T*M
#define ROI     2048
#define SPA     4
#define WORD    300
#define ROISPA  2052      // ROI+SPA
#define INW     2352      // ROI+SPA+WORD
#define HH      512
#define DD      256
#define RELIN   556       // D + WORD
#define KP1     2080      // ROISPA padded to 65*32

// ---------------- scratch (device globals; no allocation) ----------------
__device__ __half g_X16 [NROWS * KP1];                      // activations fp16
__device__ __half g_W1_s[HH * KP1], g_W1_o[HH * KP1];       // weights fp16
__device__ __half g_Y1_s[NROWS * HH], g_Y1_o[NROWS * HH];
__device__ __half g_Y2_s[NROWS * HH], g_Y2_o[NROWS * HH];
__device__ __half g_Wf_s[HH * HH], g_Wf_o[HH * HH];
__device__ __half g_Wcc_s[HH * HH], g_Wcc_o[HH * HH];
__device__ __half g_A16[NROWS * HH];   // A + bias512 folded, fp16
__device__ __half g_B16[NROWS * HH];   // B, fp16
__device__ float g_Wsum_s[HH * DD], g_Wsum_o[HH * DD];
__device__ float g_Wc_s  [HH * DD], g_Wc_o  [HH * DD];
__device__ float g_c_subj[HH], g_c_obj[HH], g_bias512[HH];
__device__ float g_bf_s[HH], g_bf_o[HH], g_cvec_s[HH], g_cvec_o[HH];
__device__ __half g_W2[DD * HH];

// ---------------- helpers ----------------
__device__ __forceinline__ uint32_t smem_u32(const void* p) {
    uint32_t a;
    asm("{ .reg .u64 t; cvta.to.shared.u64 t, %1; cvt.u32.u64 %0, t; }"
        : "=r"(a) : "l"(p));
    return a;
}
__device__ __forceinline__ void ldsm4(uint32_t* r, uint32_t addr) {
    asm volatile("ldmatrix.sync.aligned.m8n8.x4.shared.b16 {%0,%1,%2,%3}, [%4];"
        : "=r"(r[0]), "=r"(r[1]), "=r"(r[2]), "=r"(r[3]) : "r"(addr));
}
__device__ __forceinline__ void mma_f16(float* c, const uint32_t* a, const uint32_t* b) {
    asm volatile(
        "mma.sync.aligned.m16n8k16.row.col.f32.f16.f16.f32 "
        "{%0,%1,%2,%3}, {%4,%5,%6,%7}, {%8,%9}, {%0,%1,%2,%3};"
        : "+f"(c[0]), "+f"(c[1]), "+f"(c[2]), "+f"(c[3])
        : "r"(a[0]), "r"(a[1]), "r"(a[2]), "r"(a[3]), "r"(b[0]), "r"(b[1]));
}
__device__ __forceinline__ void cp16(uint32_t dst, const void* src) {
    asm volatile("cp.async.ca.shared.global [%0], [%1], 16;" :: "r"(dst), "l"(src));
}
__device__ __forceinline__ void cp_commit() {
    asm volatile("cp.async.commit_group;");
}
__device__ __forceinline__ void cp_wait0() {
    asm volatile("cp.async.wait_group 0;" ::: "memory");
}

// ---------------- merged conversions: pack X | W1->fp16 | W2->fp16 ----------------
#define CV_W1BLKS (HH * KP1 / 256)        // 4160
#define CV_W2BLKS (DD * HH / 256)         // 512
#define CV_BLOCKS (NROWS + CV_W1BLKS + CV_W2BLKS)   // 8768

__global__ void convert_all_kernel(const float* __restrict__ roi,
                                   const float* __restrict__ spa,
                                   const float* __restrict__ s_w1,
                                   const float* __restrict__ o_w1,
                                   const float* __restrict__ w2) {
    int b = blockIdx.x;
    if (b < NROWS) {
        int r = b;
        for (int k = threadIdx.x; k < KP1; k += 256) {
            float v = 0.f;
            if (k < ROI)         v = roi[(size_t)r * ROI + k];
            else if (k < ROISPA) v = spa[(size_t)r * SPA + (k - ROI)];
            g_X16[(size_t)r * KP1 + k] = __float2half_rn(v);
        }
    } else if (b < NROWS + CV_W1BLKS) {
        int idx = (b - NROWS) * 256 + threadIdx.x;
        int n = idx / KP1, k = idx - n * KP1;
        float vs = (k < ROISPA) ? s_w1[(size_t)n * INW + k] : 0.f;
        float vo = (k < ROISPA) ? o_w1[(size_t)n * INW + k] : 0.f;
        g_W1_s[idx] = __float2half_rn(vs);
        g_W1_o[idx] = __float2half_rn(vo);
    } else {
        int idx = (b - NROWS - CV_W1BLKS) * 256 + threadIdx.x;
        g_W2[idx] = __float2half_rn(w2[idx]);
    }
}

// ---------------- constant biases + Wsum ----------------
__global__ void pre_vec_kernel(const float* __restrict__ subj_w1, const float* __restrict__ subj_b1,
                               const float* __restrict__ obj_w1,  const float* __restrict__ obj_b1,
                               const float* __restrict__ rel_w1,  const float* __restrict__ rel_b1,
                               const float* __restrict__ subj_emb, const float* __restrict__ obj_emb,
                               const float* __restrict__ pred_emb,
                               const float* __restrict__ fuse_s_w1, const float* __restrict__ fuse_o_w1) {
    int h = blockIdx.x;
    int t = threadIdx.x;
    float s1 = 0.f, s2 = 0.f, s3 = 0.f;
    for (int w = t; w < WORD; w += 128) {
        s1 += subj_w1[(size_t)h * INW + ROISPA + w] * subj_emb[w];
        s2 += obj_w1 [(size_t)h * INW + ROISPA + w] * obj_emb[w];
        s3 += rel_w1 [(size_t)h * RELIN + DD + w]   * pred_emb[w];
    }
    for (int o = 16; o > 0; o >>= 1) {
        s1 += __shfl_down_sync(0xffffffffu, s1, o);
        s2 += __shfl_down_sync(0xffffffffu, s2, o);
        s3 += __shfl_down_sync(0xffffffffu, s3, o);
    }
    __shared__ float red[3][4];
    int wrp = t >> 5, lan = t & 31;
    if (lan == 0) { red[0][wrp] = s1; red[1][wrp] = s2; red[2][wrp] = s3; }
    __syncthreads();
    if (t == 0) {
        g_c_subj[h]  = red[0][0] + red[0][1] + red[0][2] + red[0][3] + subj_b1[h];
        g_c_obj[h]   = red[1][0] + red[1][1] + red[1][2] + red[1][3] + obj_b1[h];
        g_bias512[h] = red[2][0] + red[2][1] + red[2][2] + red[2][3] + rel_b1[h];
    }
    for (int d = t; d < DD; d += 128) {
        g_Wsum_s[h * DD + d] = fuse_s_w1[(size_t)h * (2*DD) + d] + fuse_s_w1[(size_t)h * (2*DD) + DD + d];
        g_Wsum_o[h * DD + d] = fuse_o_w1[(size_t)h * (2*DD) + d] + fuse_o_w1[(size_t)h * (2*DD) + DD + d];
    }
}

// ---------------- tiled NN GEMM: C = A(MxK) @ B(KxN) ----------------
template<bool F16OUT>
__global__ __launch_bounds__(256)
void nn_gemm_kernel(const float* __restrict__ A0, const float* __restrict__ B0,
                    float* __restrict__ C0, __half* __restrict__ Ch0,
                    const float* __restrict__ A1, const float* __restrict__ B1,
                    float* __restrict__ C1, __half* __restrict__ Ch1,
                    int N, int K, int lda, int ldb) {
    __shared__ float Ask[16][68];
    __shared__ float Bs [16][68];
    const int br = blockIdx.z;
    const float* A = br ? A1 : A0;
    const float* B = br ? B1 : B0;
    const int m0 = blockIdx.y * 64, n0 = blockIdx.x * 64;
    const int tid = threadIdx.x;
    const int tr = tid >> 4, tc = tid & 15;
    float acc[4][4];
    #pragma unroll
    for (int i = 0; i < 4; i++)
        #pragma unroll
        for (int j = 0; j < 4; j++) acc[i][j] = 0.f;

    for (int k0 = 0; k0 < K; k0 += 16) {
        {
            int r = tid >> 2, kq = (tid & 3) * 4;
            float4 v = *reinterpret_cast<const float4*>(&A[(size_t)(m0 + r) * lda + k0 + kq]);
            Ask[kq + 0][r] = v.x; Ask[kq + 1][r] = v.y;
            Ask[kq + 2][r] = v.z; Ask[kq + 3][r] = v.w;
        }
        {
            int k = tid >> 4, nq = (tid & 15) * 4;
            float4 v = *reinterpret_cast<const float4*>(&B[(size_t)(k0 + k) * ldb + n0 + nq]);
            *reinterpret_cast<float4*>(&Bs[k][nq]) = v;
        }
        __syncthreads();
        #pragma unroll
        for (int k = 0; k < 16; k++) {
            float a[4], b[4];
            *reinterpret_cast<float4*>(a) = *reinterpret_cast<const float4*>(&Ask[k][tr * 4]);
            *reinterpret_cast<float4*>(b) = *reinterpret_cast<const float4*>(&Bs[k][tc * 4]);
            #pragma unroll
            for (int i = 0; i < 4; i++)
                #pragma unroll
                for (int j = 0; j < 4; j++)
                    acc[i][j] = fmaf(a[i], b[j], acc[i][j]);
        }
        __syncthreads();
    }

    if (F16OUT) {
        __half* Ch = br ? Ch1 : Ch0;
        #pragma unroll
        for (int i = 0; i < 4; i++)
            #pragma unroll
            for (int j = 0; j < 4; j++) {
                size_t off = (size_t)(m0 + tr * 4 + i) * N + n0 + tc * 4 + j;
                Ch[off] = __float2half_rn(acc[i][j]);
            }
    } else {
        float* C = br ? C1 : C0;
        #pragma unroll
        for (int i = 0; i < 4; i++)
            #pragma unroll
            for (int j = 0; j < 4; j++)
                C[(size_t)(m0 + tr * 4 + i) * N + n0 + tc * 4 + j] = acc[i][j];
    }
}

// ---------------- batched small GEMV for bias folds ----------------
__global__ void gemv4_kernel(const float* __restrict__ subj_b2, const float* __restrict__ obj_b2,
                             const float* __restrict__ fuse_s_b1, const float* __restrict__ fuse_o_b1,
                             const float* __restrict__ fuse_s_b2, const float* __restrict__ fuse_o_b2) {
    int which = blockIdx.y;
    const float *A, *v, *add; float* o;
    if      (which == 0) { A = g_Wsum_s; v = subj_b2;  add = fuse_s_b1; o = g_bf_s; }
    else if (which == 1) { A = g_Wsum_o; v = obj_b2;   add = fuse_o_b1; o = g_bf_o; }
    else if (which == 2) { A = g_Wc_s;   v = fuse_s_b2; add = g_bias512; o = g_cvec_s; }
    else                 { A = g_Wc_o;   v = fuse_o_b2; add = nullptr;  o = g_cvec_o; }
    int h = blockIdx.x * 8 + (threadIdx.x >> 5);
    int lane = threadIdx.x & 31;
    float s = 0.f;
    for (int d = lane; d < DD; d += 32) s += A[h * DD + d] * v[d];
    #pragma unroll
    for (int off = 16; off > 0; off >>= 1) s += __shfl_down_sync(0xffffffffu, s, off);
    if (lane == 0) o[h] = s + (add ? add[h] : 0.f);
}

// ================= chain HMMA GEMM (fp16, cp.async double-buffered) ====
#define CPSTR   80
#define CBUFSZ  20480
#define CSMEM   (512 + 2 * CBUFSZ)   // 41472

template<bool RELU, bool F16OUT>
__global__ __launch_bounds__(256, 2)
void chain_hmma_kernel(const __half* __restrict__ X0, const __half* __restrict__ X1,
                       int ldx,
                       const __half* __restrict__ W0, const __half* __restrict__ W1,
                       const float* __restrict__ bias0, const float* __restrict__ bias1,
                       float* __restrict__ C0, float* __restrict__ C1,
                       __half* __restrict__ Co0, __half* __restrict__ Co1,
                       int N, int K) {
    extern __shared__ char smem[];
    const uint32_t su = smem_u32(smem);
    float* biasS = reinterpret_cast<float*>(smem);

    const int tid  = threadIdx.x;
    const int wid  = tid >> 5;
    const int lane = tid & 31;
    const int wm   = wid >> 1;
    const int wn   = wid & 1;
    const int n0   = blockIdx.x * 128;
    const int m0   = blockIdx.y * 128;
    const int br   = blockIdx.z;

    const __half* X = br ? X1 : X0;
    const __half* W = br ? W1 : W0;
    const float* bias = br ? bias1 : bias0;

    if (tid < 128) biasS[tid] = bias[n0 + tid];

    auto stage = [&](int k0, int b) {
        uint32_t base = su + 512 + (uint32_t)b * CBUFSZ;
        #pragma unroll
        for (int e = 0; e < 2; e++) {
            int idx = e * 256 + tid;
            int r = idx >> 2, q = idx & 3;
            cp16(base +         r * CPSTR + q * 16, X + (size_t)(m0 + r) * ldx + k0 + q * 8);
            cp16(base + 10240 + r * CPSTR + q * 16, W + (size_t)(n0 + r) * K + k0 + q * 8);
        }
    };

    const uint32_t h_off = (uint32_t)((lane & 15) * CPSTR + (lane >> 4) * 16);
    const uint32_t w_off = (uint32_t)(((lane & 7) + ((lane >> 4) << 3)) * CPSTR
                                      + ((lane >> 3) & 1) * 16);

    float acc[2][8][4];
    #pragma unroll
    for (int mb = 0; mb < 2; mb++)
        #pragma unroll
        for (int nb = 0; nb < 8; nb++)
            #pragma unroll
            for (int q = 0; q < 4; q++) acc[mb][nb][q] = 0.f;

    stage(0, 0); cp_commit();
    const int nk = K / 32;

    for (int c = 0; c < nk; c++) {
        cp_wait0();
        __syncthreads();
        if (c + 1 < nk) { stage((c + 1) * 32, (c + 1) & 1); cp_commit(); }

        const uint32_t base = su + 512 + (uint32_t)(c & 1) * CBUFSZ;
        #pragma unroll
        for (int ks = 0; ks < 2; ks++) {
            uint32_t a[2][4];
            const uint32_t hbase = base + wm * (32 * CPSTR) + ks * 32 + h_off;
            ldsm4(a[0], hbase);
            ldsm4(a[1], hbase + 16 * CPSTR);
            const uint32_t wbase = base + 10240 + wn * (64 * CPSTR) + ks * 32 + w_off;
            #pragma unroll
            for (int g = 0; g < 4; g++) {
                uint32_t b[4];
                ldsm4(b, wbase + g * (16 * CPSTR));
                mma_f16(acc[0][g * 2 + 0], a[0], b);
                mma_f16(acc[0][g * 2 + 1], a[0], b + 2);
                mma_f16(acc[1][g * 2 + 0], a[1], b);
                mma_f16(acc[1][g * 2 + 1], a[1], b + 2);
            }
        }
    }

    // ---- epilogue ----
    const int qr = lane >> 2, qc = (lane & 3) * 2;
    float* C = br ? C1 : C0;
    __half* Co = br ? Co1 : Co0;
    #pragma unroll
    for (int mb = 0; mb < 2; mb++) {
        int rA = m0 + wm * 32 + mb * 16 + qr;
        int rB = rA + 8;
        #pragma unroll
        for (int nb = 0; nb < 8; nb++) {
            int ln = qc + wn * 64 + nb * 8;
            int col = n0 + ln;
            float vA0 = acc[mb][nb][0] + biasS[ln];
            float vA1 = acc[mb][nb][1] + biasS[ln + 1];
            float vB0 = acc[mb][nb][2] + biasS[ln];
            float vB1 = acc[mb][nb][3] + biasS[ln + 1];
            if (RELU) {
                vA0 = fmaxf(vA0, 0.f); vA1 = fmaxf(vA1, 0.f);
                vB0 = fmaxf(vB0, 0.f); vB1 = fmaxf(vB1, 0.f);
            }
            if (F16OUT) {
                *reinterpret_cast<__half2*>(&Co[(size_t)rA * N + col]) = __floats2half2_rn(vA0, vA1);
                *reinterpret_cast<__half2*>(&Co[(size_t)rB * N + col]) = __floats2half2_rn(vB0, vB1);
            } else {
                *reinterpret_cast<float2*>(&C[(size_t)rA * N + col]) = make_float2(vA0, vA1);
                *reinterpret_cast<float2*>(&C[(size_t)rB * N + col]) = make_float2(vB0, vB1);
            }
        }
    }
}

// ================= HMMA pairwise kernel (fp16 A/B, register-built a-frags) =====
// smem layout:
//  0      b2        512
//  512    buf0 { A 2x64B=128 | B 64x80B=5120 | W 128x80B=10240 } = 15488
//  16000  buf1
#define PW_BUF0  512
#define PW_BUFSZ 15488
#define PSTR     80
#define BSTR     40      // B stride in halves (80B) - conflict-free
#define PSMEM    (PW_BUF0 + 2 * PW_BUFSZ)   // 31488

__global__ __launch_bounds__(256, 2)
void pairwise_hmma_kernel(const float* __restrict__ b2v,
                          float* __restrict__ out) {
    extern __shared__ char smem[];
    const uint32_t su = smem_u32(smem);
    float* bs2 = reinterpret_cast<float*>(smem);

    const int tid  = threadIdx.x;
    const int wid  = tid >> 5;
    const int lane = tid & 31;
    const int wm   = wid >> 1;
    const int wn   = wid & 1;
    const int qr   = lane >> 2;

    const int n0  = blockIdx.x * 128;
    const int ib2 = blockIdx.y * 2;
    const int t   = blockIdx.z;

    if (tid < 128) bs2[tid] = b2v[n0 + tid];

    const size_t arow0 = (size_t)(t * 64 + ib2) * HH;
    const size_t brow0 = (size_t)(t * 64) * HH;

    auto stage = [&](int k0, int b) {
        uint32_t base = su + PW_BUF0 + (uint32_t)b * PW_BUFSZ;
        if (tid < 8) {                             // A (fp16, bias folded): 2 rows x 32
            int r = tid >> 2, q = tid & 3;
            cp16(base + r * 64 + q * 16, g_A16 + arow0 + (size_t)r * HH + k0 + q * 8);
        }
        {                                          // B (fp16): 64 rows x 32, stride 80B
            int j = tid >> 2, q = tid & 3;
            cp16(base + 128 + j * 80 + q * 16, g_B16 + brow0 + (size_t)j * HH + k0 + q * 8);
        }
        #pragma unroll
        for (int e = 0; e < 2; e++) {              // W: 128 x 32 fp16, stride 80B
            int idx = e * 256 + tid;
            int n = idx >> 2, q = idx & 3;
            cp16(base + 5248 + n * PSTR + q * 16, g_W2 + (size_t)(n0 + n) * HH + k0 + q * 8);
        }
    };

    const uint32_t w_off = (uint32_t)(((lane & 7) + ((lane >> 4) << 3)) * PSTR
                                      + ((lane >> 3) & 1) * 16);
    const int i_warp = (wm >= 2) ? 1 : 0;          // A row index for this warp's band

    float acc[2][8][4];
    #pragma unroll
    for (int mb = 0; mb < 2; mb++)
        #pragma unroll
        for (int nb = 0; nb < 8; nb++)
            #pragma unroll
            for (int q = 0; q < 4; q++) acc[mb][nb][q] = 0.f;

    stage(0, 0); cp_commit();
    const __half2 hz = __floats2half2_rn(0.f, 0.f);

    for (int c = 0; c < 16; c++) {
        cp_wait0();
        __syncthreads();                 // buf(c) staged; all reads of buf(c-1) done

        const uint32_t bo = PW_BUF0 + (uint32_t)(c & 1) * PW_BUFSZ;
        const __half* AsB = reinterpret_cast<const __half*>(smem + bo);          // stride 32
        const __half* BsB = reinterpret_cast<const __half*>(smem + bo + 128);    // stride 40
        const uint32_t base = su + bo;

        if (c + 1 < 16) { stage((c + 1) * 32, (c + 1) & 1); cp_commit(); }

        #pragma unroll
        for (int ks = 0; ks < 2; ks++) {
            const int kb = ks * 16 + (lane & 3) * 2;
            const __half2 av0 = *reinterpret_cast<const __half2*>(&AsB[i_warp * 32 + kb]);
            const __half2 av1 = *reinterpret_cast<const __half2*>(&AsB[i_warp * 32 + kb + 8]);
            uint32_t a[2][4];
            #pragma unroll
            for (int mb = 0; mb < 2; mb++) {
                const int j0 = ((wm * 32 + mb * 16) & 63) + qr;
                __half2 b00 = *reinterpret_cast<const __half2*>(&BsB[j0 * BSTR + kb]);
                __half2 b10 = *reinterpret_cast<const __half2*>(&BsB[(j0 + 8) * BSTR + kb]);
                __half2 b01 = *reinterpret_cast<const __half2*>(&BsB[j0 * BSTR + kb + 8]);
                __half2 b11 = *reinterpret_cast<const __half2*>(&BsB[(j0 + 8) * BSTR + kb + 8]);
                __half2 h0 = __hmax2(__hsub2(av0, b00), hz);
                __half2 h1 = __hmax2(__hsub2(av0, b10), hz);
                __half2 h2 = __hmax2(__hsub2(av1, b01), hz);
                __half2 h3 = __hmax2(__hsub2(av1, b11), hz);
                a[mb][0] = *reinterpret_cast<uint32_t*>(&h0);
                a[mb][1] = *reinterpret_cast<uint32_t*>(&h1);
                a[mb][2] = *reinterpret_cast<uint32_t*>(&h2);
                a[mb][3] = *reinterpret_cast<uint32_t*>(&h3);
            }
            const uint32_t wbase = base + 5248 + wn * (64 * PSTR) + ks * 32 + w_off;
            #pragma unroll
            for (int g = 0; g < 4; g++) {
                uint32_t b[4];
                ldsm4(b, wbase + g * (16 * PSTR));
                mma_f16(acc[0][g * 2 + 0], a[0], b);
                mma_f16(acc[0][g * 2 + 1], a[0], b + 2);
                mma_f16(acc[1][g * 2 + 0], a[1], b);
                mma_f16(acc[1][g * 2 + 1], a[1], b + 2);
            }
        }
    }

    const int qc = (lane & 3) * 2;
    #pragma unroll
    for (int mb = 0; mb < 2; mb++) {
        int rA = wm * 32 + mb * 16 + qr;
        int rB = rA + 8;
        float* oA = out + ((size_t)(t * 64 + ib2 + (rA >> 6)) * 64 + (rA & 63)) * 256
                        + n0 + wn * 64 + qc;
        float* oB = out + ((size_t)(t * 64 + ib2 + (rB >> 6)) * 64 + (rB & 63)) * 256
                        + n0 + wn * 64 + qc;
        #pragma unroll
        for (int nb = 0; nb < 8; nb++) {
            int ln = wn * 64 + nb * 8 + qc;
            float2 vA = make_float2(acc[mb][nb][0] + bs2[ln],
                                    acc[mb][nb][1] + bs2[ln + 1]);
            float2 vB = make_float2(acc[mb][nb][2] + bs2[ln],
                                    acc[mb][nb][3] + bs2[ln + 1]);
            *reinterpret_cast<float2*>(oA + nb * 8) = vA;
            *reinterpret_cast<float2*>(oB + nb * 8) = vB;
        }
    }
}

// ---------------- host launch ----------------
extern "C" void kernel_launch(void* const* d_in, const int* in_sizes, int n_in,
                              void* d_out, int out_size) {
    const float* roi       = (const float*)d_in[0];
    const float* spatial   = (const float*)d_in[1];
    const float* subj_emb  = (const float*)d_in[3];
    const float* obj_emb   = (const float*)d_in[4];
    const float* pred_emb  = (const float*)d_in[5];
    const float* subj_w1   = (const float*)d_in[6];
    const float* subj_b1   = (const float*)d_in[7];
    const float* subj_w2   = (const float*)d_in[8];
    const float* subj_b2   = (const float*)d_in[9];
    const float* obj_w1    = (const float*)d_in[10];
    const float* obj_b1    = (const float*)d_in[11];
    const float* obj_w2    = (const float*)d_in[12];
    const float* obj_b2    = (const float*)d_in[13];
    const float* fuse_s_w1 = (const float*)d_in[14];
    const float* fuse_s_b1 = (const float*)d_in[15];
    const float* fuse_s_w2 = (const float*)d_in[16];
    const float* fuse_s_b2 = (const float*)d_in[17];
    const float* fuse_o_w1 = (const float*)d_in[18];
    const float* fuse_o_b1 = (const float*)d_in[19];
    const float* fuse_o_w2 = (const float*)d_in[20];
    const float* fuse_o_b2 = (const float*)d_in[21];
    const float* W_rs      = (const float*)d_in[22];
    const float* W_ro      = (const float*)d_in[23];
    const float* rel_w1    = (const float*)d_in[24];
    const float* rel_b1    = (const float*)d_in[25];
    const float* rel_w2    = (const float*)d_in[26];
    const float* rel_b2    = (const float*)d_in[27];
    float* out = (float*)d_out;

    __half *pX16, *pW1_s, *pW1_o;
    __half *pY1_s, *pY1_o, *pY2_s, *pY2_o;
    __half *pWf_s, *pWf_o, *pWcc_s, *pWcc_o;
    __half *pA16, *pB16;
    float *pWsum_s, *pWsum_o, *pWc_s, *pWc_o;
    float *pc_subj, *pc_obj, *pbf_s, *pbf_o, *pcv_s, *pcv_o;
    cudaGetSymbolAddress((void**)&pX16, g_X16);
    cudaGetSymbolAddress((void**)&pW1_s, g_W1_s);
    cudaGetSymbolAddress((void**)&pW1_o, g_W1_o);
    cudaGetSymbolAddress((void**)&pY1_s, g_Y1_s);
    cudaGetSymbolAddress((void**)&pY1_o, g_Y1_o);
    cudaGetSymbolAddress((void**)&pY2_s, g_Y2_s);
    cudaGetSymbolAddress((void**)&pY2_o, g_Y2_o);
    cudaGetSymbolAddress((void**)&pWf_s, g_Wf_s);
    cudaGetSymbolAddress((void**)&pWf_o, g_Wf_o);
    cudaGetSymbolAddress((void**)&pWcc_s, g_Wcc_s);
    cudaGetSymbolAddress((void**)&pWcc_o, g_Wcc_o);
    cudaGetSymbolAddress((void**)&pA16, g_A16);
    cudaGetSymbolAddress((void**)&pB16, g_B16);
    cudaGetSymbolAddress((void**)&pWsum_s, g_Wsum_s);
    cudaGetSymbolAddress((void**)&pWsum_o, g_Wsum_o);
    cudaGetSymbolAddress((void**)&pWc_s, g_Wc_s);
    cudaGetSymbolAddress((void**)&pWc_o, g_Wc_o);
    cudaGetSymbolAddress((void**)&pc_subj, g_c_subj);
    cudaGetSymbolAddress((void**)&pc_obj,  g_c_obj);
    cudaGetSymbolAddress((void**)&pbf_s,  g_bf_s);
    cudaGetSymbolAddress((void**)&pbf_o,  g_bf_o);
    cudaGetSymbolAddress((void**)&pcv_s,  g_cvec_s);
    cudaGetSymbolAddress((void**)&pcv_o,  g_cvec_o);

    static bool init_done = false;
    static cudaStream_t s2 = nullptr;
    static cudaEvent_t e1 = nullptr, e_pv = nullptr, e2 = nullptr;
    if (!init_done) {
        cudaFuncSetAttribute(pairwise_hmma_kernel,
                             cudaFuncAttributeMaxDynamicSharedMemorySize, PSMEM);
        cudaFuncSetAttribute(chain_hmma_kernel<true, true>,
                             cudaFuncAttributeMaxDynamicSharedMemorySize, CSMEM);
        cudaFuncSetAttribute(chain_hmma_kernel<false, true>,
                             cudaFuncAttributeMaxDynamicSharedMemorySize, CSMEM);
        cudaStreamCreateWithFlags(&s2, cudaStreamNonBlocking);
        cudaEventCreateWithFlags(&e1,  cudaEventDisableTiming);
        cudaEventCreateWithFlags(&e_pv, cudaEventDisableTiming);
        cudaEventCreateWithFlags(&e2,  cudaEventDisableTiming);
        init_done = true;
    }

    // ---- fork: weight-prep branch on s2 ----
    cudaEventRecord(e1, 0);
    cudaStreamWaitEvent(s2, e1, 0);

    pre_vec_kernel<<<HH, 128, 0, s2>>>(subj_w1, subj_b1, obj_w1, obj_b1, rel_w1, rel_b1,
                                       subj_emb, obj_emb, pred_emb, fuse_s_w1, fuse_o_w1);
    cudaEventRecord(e_pv, s2);
    nn_gemm_kernel<false><<<dim3(4, 8, 2), 256, 0, s2>>>(
        rel_w1, W_rs, pWc_s, nullptr,
        rel_w1, W_ro, pWc_o, nullptr,
        DD, DD, RELIN, DD);
    nn_gemm_kernel<true><<<dim3(8, 8, 2), 256, 0, s2>>>(
        pWsum_s, subj_w2, nullptr, pWf_s,
        pWsum_o, obj_w2,  nullptr, pWf_o,
        HH, DD, DD, HH);
    nn_gemm_kernel<true><<<dim3(8, 8, 2), 256, 0, s2>>>(
        pWc_s, fuse_s_w2, nullptr, pWcc_s,
        pWc_o, fuse_o_w2, nullptr, pWcc_o,
        HH, DD, DD, HH);
    gemv4_kernel<<<dim3(64, 4), 256, 0, s2>>>(subj_b2, obj_b2, fuse_s_b1, fuse_o_b1,
                                              fuse_s_b2, fuse_o_b2);
    cudaEventRecord(e2, s2);

    // ---- main stream: conversions then chain ----
    convert_all_kernel<<<CV_BLOCKS, 256>>>(roi, spatial, subj_w1, obj_w1, rel_w2);

    dim3 cgrid(HH / 128, NROWS / 128, 2);

    cudaStreamWaitEvent(0, e_pv, 0);
    chain_hmma_kernel<true, true><<<cgrid, 256, CSMEM>>>(
        pX16, pX16, KP1,
        pW1_s, pW1_o,
        pc_subj, pc_obj,
        nullptr, nullptr,
        pY1_s, pY1_o,
        HH, KP1);

    cudaStreamWaitEvent(0, e2, 0);
    chain_hmma_kernel<true, true><<<cgrid, 256, CSMEM>>>(
        pY1_s, pY1_o, HH,
        pWf_s, pWf_o,
        pbf_s, pbf_o,
        nullptr, nullptr,
        pY2_s, pY2_o,
        HH, HH);

    chain_hmma_kernel<false, true><<<cgrid, 256, CSMEM>>>(
        pY2_s, pY2_o, HH,
        pWcc_s, pWcc_o,
        pcv_s, pcv_o,
        nullptr, nullptr,
        pA16, pB16,
        HH, HH);

    // pairwise GEMM (HMMA fp16, register-built a-frags)
    pairwise_hmma_kernel<<<dim3(2, 32, 64), 256, PSMEM>>>(rel_b2, out);

    (void)in_sizes; (void)n_in; (void)out_size;
}